// round 3
// baseline (speedup 1.0000x reference)
#include <cuda_runtime.h>
#include <cuda_bf16.h>
#include <math.h>

#define ZD   32
#define HH   64
#define WW   64
#define HW   4096
#define CIN  32
#define CC   64
#define Z1   33
#define Z2   34
#define DI   128
#define NTOK 131072
#define DST  16
#define EPSF 1e-5f

// ---------------- scratch ----------------
__device__ float g_buf1[CC * Z1 * HW];
__device__ float g_buf2[CC * Z2 * HW];
__device__ float g_h   [CC * ZD * HW];
__device__ float g_dw  [CC * ZD * HW];
__device__ float g_pw  [CC * ZD * HW];
__device__ float g_x2t [NTOK * CC];
__device__ float g_xin [NTOK * DI];
__device__ float g_zg  [NTOK * DI];
__device__ float g_xa  [NTOK * DI];
__device__ float g_xdbl[NTOK * 36];
__device__ float g_y   [NTOK * DI];
__device__ float g_seqout[NTOK * CC];
__device__ float g_A   [DI * DST];
__device__ float g_wc  [CC * DI];

__device__ double g_dsum[4][64];
__device__ double g_dsq [4][64];
__device__ float  g_mean[4][64];
__device__ float  g_istd[4][64];

// ---------------- helpers ----------------
__device__ __forceinline__ float fsilu(float x) {
    return x * (1.f / (1.f + __expf(-x)));
}
__device__ __forceinline__ float flrelu(float x) {
    return fmaxf(x, 0.01f * x);
}

__device__ __forceinline__ void stat_reduce_256(float s, float q, int tid,
                                                double* ds, double* dq) {
#pragma unroll
    for (int o = 16; o > 0; o >>= 1) {
        s += __shfl_down_sync(0xffffffffu, s, o);
        q += __shfl_down_sync(0xffffffffu, q, o);
    }
    __shared__ float shs[8], shq[8];
    if ((tid & 31) == 0) { shs[tid >> 5] = s; shq[tid >> 5] = q; }
    __syncthreads();
    if (tid == 0) {
        float S = 0.f, Q = 0.f;
#pragma unroll
        for (int i = 0; i < 8; i++) { S += shs[i]; Q += shq[i]; }
        atomicAdd(ds, (double)S);
        atomicAdd(dq, (double)Q);
    }
}

// ---------------- service ----------------
__global__ void k_zero() {
    int tid = threadIdx.x;
    if (tid < 256) {
        ((double*)g_dsum)[tid] = 0.0;
        ((double*)g_dsq)[tid]  = 0.0;
    }
}

__global__ void k_prepA(const float* __restrict__ A_log) {
    int i = blockIdx.x * blockDim.x + threadIdx.x;
    if (i < DI * DST) g_A[i] = -expf(A_log[i]);
}

__global__ void k_fin(int which) {
    int c = threadIdx.x;
    if (c >= 64) return;
    const double counts[4] = {33.0 * 4096.0, 34.0 * 4096.0, 131072.0, 131072.0};
    double n = counts[which];
    double m = g_dsum[which][c] / n;
    double v = g_dsq[which][c] / n - m * m;
    g_mean[which][c] = (float)m;
    g_istd[which][c] = (float)(1.0 / sqrt(v + 1e-5));
}

// ---------------- conv1 ----------------
__global__ __launch_bounds__(256) void k_conv1(const float* __restrict__ x,
                                               const float* __restrict__ w) {
    const int tileR = blockIdx.x * 16;
    const int zo = blockIdx.y;
    const int co = blockIdx.z;
    __shared__ float ws[CIN * 18];
    __shared__ float ins[18 * 66];
    const int tx = threadIdx.x, ty = threadIdx.y;
    const int tid = ty * 16 + tx;
    for (int i = tid; i < CIN * 18; i += 256) ws[i] = w[co * (CIN * 18) + i];
    float a0 = 0.f, a1 = 0.f, a2 = 0.f, a3 = 0.f;
    for (int ci = 0; ci < CIN; ci++) {
        for (int kz = 0; kz < 2; kz++) {
            int zz = zo - 1 + kz;
            __syncthreads();
            bool zok = (zz >= 0 && zz < ZD);
            const float* xp = x + ((size_t)ci * ZD + zz) * HW;
            for (int i = tid; i < 18 * 66; i += 256) {
                int r = i / 66, c2 = i % 66;
                int gr = tileR + r - 1, gc = c2 - 1;
                float v = 0.f;
                if (zok && gr >= 0 && gr < HH && gc >= 0 && gc < WW)
                    v = xp[gr * WW + gc];
                ins[i] = v;
            }
            __syncthreads();
            const float* wp = ws + ci * 18 + kz * 9;
#pragma unroll
            for (int ky = 0; ky < 3; ky++) {
                const float* rp = ins + (ty + ky) * 66 + (tx << 2);
                float v0 = rp[0], v1 = rp[1], v2 = rp[2], v3 = rp[3], v4 = rp[4], v5 = rp[5];
                float w0 = wp[3 * ky], w1 = wp[3 * ky + 1], w2 = wp[3 * ky + 2];
                a0 = fmaf(w0, v0, fmaf(w1, v1, fmaf(w2, v2, a0)));
                a1 = fmaf(w0, v1, fmaf(w1, v2, fmaf(w2, v3, a1)));
                a2 = fmaf(w0, v2, fmaf(w1, v3, fmaf(w2, v4, a2)));
                a3 = fmaf(w0, v3, fmaf(w1, v4, fmaf(w2, v5, a3)));
            }
        }
    }
    int gr = tileR + ty, gc0 = tx << 2;
    *(float4*)(g_buf1 + ((size_t)co * Z1 + zo) * HW + gr * WW + gc0) =
        make_float4(a0, a1, a2, a3);
    float s = a0 + a1 + a2 + a3;
    float q = a0 * a0 + a1 * a1 + a2 * a2 + a3 * a3;
    __syncthreads();
    stat_reduce_256(s, q, tid, &g_dsum[0][co], &g_dsq[0][co]);
}

// ---------------- conv2 ----------------
__global__ __launch_bounds__(256) void k_conv2(const float* __restrict__ w,
                                               const float* __restrict__ gg,
                                               const float* __restrict__ bb) {
    const int tileR = blockIdx.x * 16;
    const int zo = blockIdx.y;
    const int co = blockIdx.z;
    __shared__ float ws[CC * 18];
    __shared__ float ins[18 * 66];
    const int tx = threadIdx.x, ty = threadIdx.y;
    const int tid = ty * 16 + tx;
    for (int i = tid; i < CC * 18; i += 256) ws[i] = w[co * (CC * 18) + i];
    float a0 = 0.f, a1 = 0.f, a2 = 0.f, a3 = 0.f;
    for (int ci = 0; ci < CC; ci++) {
        float scale = g_istd[0][ci] * gg[ci];
        float shift = bb[ci] - g_mean[0][ci] * scale;
        for (int kz = 0; kz < 2; kz++) {
            int zz = zo - 1 + kz;
            __syncthreads();
            bool zok = (zz >= 0 && zz < Z1);
            const float* xp = g_buf1 + ((size_t)ci * Z1 + zz) * HW;
            for (int i = tid; i < 18 * 66; i += 256) {
                int r = i / 66, c2 = i % 66;
                int gr = tileR + r - 1, gc = c2 - 1;
                float v = 0.f;
                if (zok && gr >= 0 && gr < HH && gc >= 0 && gc < WW) {
                    float nv = fmaf(xp[gr * WW + gc], scale, shift);
                    v = fmaxf(nv, 0.01f * nv);
                }
                ins[i] = v;
            }
            __syncthreads();
            const float* wp = ws + ci * 18 + kz * 9;
#pragma unroll
            for (int ky = 0; ky < 3; ky++) {
                const float* rp = ins + (ty + ky) * 66 + (tx << 2);
                float v0 = rp[0], v1 = rp[1], v2 = rp[2], v3 = rp[3], v4 = rp[4], v5 = rp[5];
                float w0 = wp[3 * ky], w1 = wp[3 * ky + 1], w2 = wp[3 * ky + 2];
                a0 = fmaf(w0, v0, fmaf(w1, v1, fmaf(w2, v2, a0)));
                a1 = fmaf(w0, v1, fmaf(w1, v2, fmaf(w2, v3, a1)));
                a2 = fmaf(w0, v2, fmaf(w1, v3, fmaf(w2, v4, a2)));
                a3 = fmaf(w0, v3, fmaf(w1, v4, fmaf(w2, v5, a3)));
            }
        }
    }
    int gr = tileR + ty, gc0 = tx << 2;
    *(float4*)(g_buf2 + ((size_t)co * Z2 + zo) * HW + gr * WW + gc0) =
        make_float4(a0, a1, a2, a3);
    float s = a0 + a1 + a2 + a3;
    float q = a0 * a0 + a1 * a1 + a2 * a2 + a3 * a3;
    __syncthreads();
    stat_reduce_256(s, q, tid, &g_dsum[1][co], &g_dsq[1][co]);
}

// ---------------- h = lrelu(inorm2(buf2[:, :32])) ----------------
__global__ __launch_bounds__(256) void k_h(const float* __restrict__ gg,
                                           const float* __restrict__ bb) {
    int i4 = blockIdx.x * 256 + threadIdx.x;
    int base = i4 * 4;
    int c = base >> 17;
    int off = base & 131071;
    float scale = g_istd[1][c] * gg[c];
    float shift = bb[c] - g_mean[1][c] * scale;
    float4 r = *(const float4*)(g_buf2 + (size_t)c * (Z2 * HW) + off);
    float4 o;
    o.x = flrelu(fmaf(r.x, scale, shift));
    o.y = flrelu(fmaf(r.y, scale, shift));
    o.z = flrelu(fmaf(r.z, scale, shift));
    o.w = flrelu(fmaf(r.w, scale, shift));
    *(float4*)(g_h + base) = o;
}

// ---------------- depthwise 3x3 spatial ----------------
__global__ __launch_bounds__(256) void k_dw(const float* __restrict__ w) {
    const int tileR = blockIdx.x * 16;
    const int z = blockIdx.y;
    const int c = blockIdx.z;
    __shared__ float ins[18 * 66];
    const int tx = threadIdx.x, ty = threadIdx.y;
    const int tid = ty * 16 + tx;
    float wv[9];
#pragma unroll
    for (int i = 0; i < 9; i++) wv[i] = __ldg(w + c * 9 + i);
    const float* xp = g_h + ((size_t)c * ZD + z) * HW;
    for (int i = tid; i < 18 * 66; i += 256) {
        int r = i / 66, c2 = i % 66;
        int gr = tileR + r - 1, gc = c2 - 1;
        float v = 0.f;
        if (gr >= 0 && gr < HH && gc >= 0 && gc < WW) v = xp[gr * WW + gc];
        ins[i] = v;
    }
    __syncthreads();
    float a0 = 0.f, a1 = 0.f, a2 = 0.f, a3 = 0.f;
#pragma unroll
    for (int ky = 0; ky < 3; ky++) {
        const float* rp = ins + (ty + ky) * 66 + (tx << 2);
        float v0 = rp[0], v1 = rp[1], v2 = rp[2], v3 = rp[3], v4 = rp[4], v5 = rp[5];
        float w0 = wv[3 * ky], w1 = wv[3 * ky + 1], w2 = wv[3 * ky + 2];
        a0 = fmaf(w0, v0, fmaf(w1, v1, fmaf(w2, v2, a0)));
        a1 = fmaf(w0, v1, fmaf(w1, v2, fmaf(w2, v3, a1)));
        a2 = fmaf(w0, v2, fmaf(w1, v3, fmaf(w2, v4, a2)));
        a3 = fmaf(w0, v3, fmaf(w1, v4, fmaf(w2, v5, a3)));
    }
    int gr = tileR + ty, gc0 = tx << 2;
    *(float4*)(g_dw + ((size_t)c * ZD + z) * HW + gr * WW + gc0) =
        make_float4(a0, a1, a2, a3);
}

// ---------------- pointwise 64x64 ----------------
__global__ __launch_bounds__(256) void k_pw(const float* __restrict__ w) {
    __shared__ float wsm[64 * 64];
    int tid = threadIdx.x;
    for (int i = tid; i < 4096; i += 256) wsm[i] = w[i];
    __syncthreads();
    int p = blockIdx.x * 256 + tid;
    float acc[64];
#pragma unroll
    for (int co = 0; co < 64; co++) acc[co] = 0.f;
    for (int ci = 0; ci < 64; ci++) {
        float v = g_dw[(size_t)ci * (ZD * HW) + p];
#pragma unroll
        for (int co = 0; co < 64; co++) acc[co] = fmaf(wsm[co * 64 + ci], v, acc[co]);
    }
#pragma unroll
    for (int co = 0; co < 64; co++) g_pw[(size_t)co * (ZD * HW) + p] = acc[co];
}

// ---------------- stats for inorm_r ----------------
__global__ __launch_bounds__(256) void k_statsR() {
    int c = blockIdx.x;
    int tid = threadIdx.x;
    size_t base = (size_t)c * (ZD * HW) + (size_t)blockIdx.y * 32768;
    float s = 0.f, q = 0.f;
    for (int i = tid; i < 32768; i += 256) {
        float v = g_pw[base + i];
        s += v; q += v * v;
    }
    stat_reduce_256(s, q, tid, &g_dsum[2][c], &g_dsq[2][c]);
}

// ---------------- x2 + transpose to token layout ----------------
__global__ __launch_bounds__(256) void k_x2t(const float* __restrict__ gg,
                                             const float* __restrict__ bb) {
    int z = blockIdx.y, n0 = blockIdx.x * 32, tid = threadIdx.x;
    __shared__ float sm[64][33];
    for (int idx = tid; idx < 2048; idx += 256) {
        int c = idx >> 5, nn = idx & 31;
        size_t off = (size_t)c * (ZD * HW) + (size_t)z * HW + n0 + nn;
        float scale = g_istd[2][c] * gg[c];
        float shift = bb[c] - g_mean[2][c] * scale;
        float v = fmaf(g_pw[off], scale, shift);
        sm[c][nn] = g_h[off] + fsilu(v);
    }
    __syncthreads();
    for (int idx = tid; idx < 2048; idx += 256) {
        int nn = idx >> 6, c = idx & 63;
        size_t t = (size_t)(n0 + nn) * ZD + z;
        g_x2t[t * 64 + c] = sm[c][nn];
    }
}

// ---------------- LN + in_proj ----------------
__global__ __launch_bounds__(256) void k_inproj(const float* __restrict__ W,
                                                const float* __restrict__ lg,
                                                const float* __restrict__ lb) {
    __shared__ float tok[64][65];
    __shared__ float wsm[64][65];
    int tid = threadIdx.x;
    int t0 = blockIdx.x * 64;
    int wi = tid >> 5, lane = tid & 31;
    float g0 = lg[lane], g1 = lg[lane + 32], b0 = lb[lane], b1 = lb[lane + 32];
    for (int tt = wi; tt < 64; tt += 8) {
        int t = t0 + tt;
        float v0 = g_x2t[(size_t)t * 64 + lane];
        float v1 = g_x2t[(size_t)t * 64 + lane + 32];
        float s = v0 + v1, q = v0 * v0 + v1 * v1;
#pragma unroll
        for (int o = 16; o > 0; o >>= 1) {
            s += __shfl_xor_sync(0xffffffffu, s, o);
            q += __shfl_xor_sync(0xffffffffu, q, o);
        }
        float mean = s * (1.f / 64.f);
        float var = q * (1.f / 64.f) - mean * mean;
        float istd = rsqrtf(var + EPSF);
        tok[tt][lane]      = (v0 - mean) * istd * g0 + b0;
        tok[tt][lane + 32] = (v1 - mean) * istd * g1 + b1;
    }
    int tidt = tid >> 4, tidj = tid & 15;
    for (int jc = 0; jc < 4; jc++) {
        __syncthreads();
        for (int idx = tid; idx < 4096; idx += 256) {
            int jr = idx >> 6, c = idx & 63;
            wsm[jr][c] = W[(jc * 64 + jr) * 64 + c];
        }
        __syncthreads();
        float acc[4][4] = {};
#pragma unroll 4
        for (int c = 0; c < 64; c++) {
            float a0 = tok[tidt * 4 + 0][c], a1 = tok[tidt * 4 + 1][c];
            float a2 = tok[tidt * 4 + 2][c], a3 = tok[tidt * 4 + 3][c];
            float w0 = wsm[tidj * 4 + 0][c], w1 = wsm[tidj * 4 + 1][c];
            float w2 = wsm[tidj * 4 + 2][c], w3 = wsm[tidj * 4 + 3][c];
            acc[0][0] = fmaf(a0, w0, acc[0][0]); acc[0][1] = fmaf(a0, w1, acc[0][1]);
            acc[0][2] = fmaf(a0, w2, acc[0][2]); acc[0][3] = fmaf(a0, w3, acc[0][3]);
            acc[1][0] = fmaf(a1, w0, acc[1][0]); acc[1][1] = fmaf(a1, w1, acc[1][1]);
            acc[1][2] = fmaf(a1, w2, acc[1][2]); acc[1][3] = fmaf(a1, w3, acc[1][3]);
            acc[2][0] = fmaf(a2, w0, acc[2][0]); acc[2][1] = fmaf(a2, w1, acc[2][1]);
            acc[2][2] = fmaf(a2, w2, acc[2][2]); acc[2][3] = fmaf(a2, w3, acc[2][3]);
            acc[3][0] = fmaf(a3, w0, acc[3][0]); acc[3][1] = fmaf(a3, w1, acc[3][1]);
            acc[3][2] = fmaf(a3, w2, acc[3][2]); acc[3][3] = fmaf(a3, w3, acc[3][3]);
        }
#pragma unroll
        for (int i = 0; i < 4; i++) {
            size_t t = t0 + tidt * 4 + i;
            float4 v = make_float4(acc[i][0], acc[i][1], acc[i][2], acc[i][3]);
            if (jc < 2) *(float4*)(g_xin + t * 128 + jc * 64 + tidj * 4) = v;
            else        *(float4*)(g_zg  + t * 128 + (jc - 2) * 64 + tidj * 4) = v;
        }
    }
}

// ---------------- causal conv1d + silu ----------------
__global__ __launch_bounds__(128) void k_conv1d(const float* __restrict__ w,
                                                const float* __restrict__ b) {
    int n = blockIdx.x, d = threadIdx.x;
    float4 wv = ((const float4*)w)[d];
    float bias = b[d];
    float x0 = 0.f, x1 = 0.f, x2v = 0.f;
    size_t base = (size_t)n * ZD * DI + d;
#pragma unroll 4
    for (int z = 0; z < ZD; z++) {
        float xn = g_xin[base + (size_t)z * DI];
        float v = fmaf(wv.x, x0, fmaf(wv.y, x1, fmaf(wv.z, x2v, fmaf(wv.w, xn, bias))));
        g_xa[base + (size_t)z * DI] = fsilu(v);
        x0 = x1; x1 = x2v; x2v = xn;
    }
}

// ---------------- x_proj ----------------
__global__ __launch_bounds__(576) void k_xproj(const float* __restrict__ W) {
    __shared__ float xs[16][129];
    __shared__ float wx[36][129];
    int tid = threadIdx.x;
    int t0 = blockIdx.x * 16;
    for (int idx = tid; idx < 16 * 128; idx += 576) {
        int r = idx >> 7, dd = idx & 127;
        xs[r][dd] = g_xa[(size_t)(t0 + r) * DI + dd];
    }
    for (int idx = tid; idx < 36 * 128; idx += 576) {
        int j = idx >> 7, dd = idx & 127;
        wx[j][dd] = W[idx];
    }
    __syncthreads();
    int j = tid % 36, tl = tid / 36;
    float acc = 0.f;
#pragma unroll 8
    for (int dd = 0; dd < 128; dd++) acc = fmaf(xs[tl][dd], wx[j][dd], acc);
    g_xdbl[(size_t)(t0 + tl) * 36 + j] = acc;
}

// ---------------- dt + selective scan + gate ----------------
__global__ __launch_bounds__(128) void k_scan(const float* __restrict__ dtw,
                                              const float* __restrict__ dtb,
                                              const float* __restrict__ Dp_) {
    int n = blockIdx.x, d = threadIdx.x;
    float4 wdt = ((const float4*)dtw)[d];
    float bdt = dtb[d], Dp = Dp_[d];
    float A[DST];
    bool fast = true;
#pragma unroll
    for (int s = 0; s < DST; s++) {
        A[s] = g_A[d * DST + s];
        fast = fast && (fabsf(A[s] + (float)(s + 1)) <= 2e-6f * (float)(s + 1));
    }
    float st[DST];
#pragma unroll
    for (int s = 0; s < DST; s++) st[s] = 0.f;
    __shared__ float xd[40];
    size_t tb = (size_t)n * ZD;
    for (int z = 0; z < ZD; z++) {
        size_t t = tb + z;
        __syncthreads();
        if (d < 36) xd[d] = g_xdbl[t * 36 + d];
        __syncthreads();
        float pre = fmaf(wdt.x, xd[0], fmaf(wdt.y, xd[1],
                    fmaf(wdt.z, xd[2], fmaf(wdt.w, xd[3], bdt))));
        float dt = (pre > 15.f) ? pre : log1pf(__expf(pre));
        float u = g_xa[t * DI + d];
        float du = dt * u;
        float y = 0.f;
        if (fast) {
            float E = __expf(-dt);
            float ep = E;
#pragma unroll
            for (int s = 0; s < DST; s++) {
                st[s] = fmaf(ep, st[s], du * xd[4 + s]);
                y = fmaf(st[s], xd[20 + s], y);
                ep *= E;
            }
        } else {
#pragma unroll
            for (int s = 0; s < DST; s++) {
                float e = __expf(dt * A[s]);
                st[s] = fmaf(e, st[s], du * xd[4 + s]);
                y = fmaf(st[s], xd[20 + s], y);
            }
        }
        float zg = g_zg[t * DI + d];
        g_y[t * DI + d] = fmaf(Dp, u, y) * fsilu(zg);
    }
}

// ---------------- Wc = proj_w @ out_proj_w ----------------
__global__ __launch_bounds__(256) void k_wc(const float* __restrict__ op,
                                            const float* __restrict__ pj) {
    int tid = threadIdx.x;
    for (int idx = tid; idx < 64 * 128; idx += 256) {
        int o = idx >> 7, dd = idx & 127;
        float acc = 0.f;
        for (int c = 0; c < 64; c++)
            acc = fmaf(pj[o * 64 + c], op[c * 128 + dd], acc);
        g_wc[idx] = acc;
    }
}

// ---------------- seqout = y @ Wc^T + proj_b ----------------
__global__ __launch_bounds__(256) void k_outproj(const float* __restrict__ pb) {
    __shared__ float tok[64][65];
    __shared__ float wsm[64][65];
    int tid = threadIdx.x;
    int t0 = blockIdx.x * 64;
    int tidt = tid >> 4, tidj = tid & 15;
    float acc[4][4] = {};
    for (int kc = 0; kc < 2; kc++) {
        __syncthreads();
        for (int idx = tid; idx < 4096; idx += 256) {
            int r = idx >> 6, k = idx & 63;
            tok[r][k] = g_y[(size_t)(t0 + r) * DI + kc * 64 + k];
            wsm[r][k] = g_wc[r * DI + kc * 64 + k];
        }
        __syncthreads();
#pragma unroll 4
        for (int k = 0; k < 64; k++) {
            float a0 = tok[tidt * 4 + 0][k], a1 = tok[tidt * 4 + 1][k];
            float a2 = tok[tidt * 4 + 2][k], a3 = tok[tidt * 4 + 3][k];
            float w0 = wsm[tidj * 4 + 0][k], w1 = wsm[tidj * 4 + 1][k];
            float w2 = wsm[tidj * 4 + 2][k], w3 = wsm[tidj * 4 + 3][k];
            acc[0][0] = fmaf(a0, w0, acc[0][0]); acc[0][1] = fmaf(a0, w1, acc[0][1]);
            acc[0][2] = fmaf(a0, w2, acc[0][2]); acc[0][3] = fmaf(a0, w3, acc[0][3]);
            acc[1][0] = fmaf(a1, w0, acc[1][0]); acc[1][1] = fmaf(a1, w1, acc[1][1]);
            acc[1][2] = fmaf(a1, w2, acc[1][2]); acc[1][3] = fmaf(a1, w3, acc[1][3]);
            acc[2][0] = fmaf(a2, w0, acc[2][0]); acc[2][1] = fmaf(a2, w1, acc[2][1]);
            acc[2][2] = fmaf(a2, w2, acc[2][2]); acc[2][3] = fmaf(a2, w3, acc[2][3]);
            acc[3][0] = fmaf(a3, w0, acc[3][0]); acc[3][1] = fmaf(a3, w1, acc[3][1]);
            acc[3][2] = fmaf(a3, w2, acc[3][2]); acc[3][3] = fmaf(a3, w3, acc[3][3]);
        }
    }
#pragma unroll
    for (int i = 0; i < 4; i++) {
        size_t t = t0 + tidt * 4 + i;
        float4 v;
        v.x = acc[i][0] + pb[tidj * 4 + 0];
        v.y = acc[i][1] + pb[tidj * 4 + 1];
        v.z = acc[i][2] + pb[tidj * 4 + 2];
        v.w = acc[i][3] + pb[tidj * 4 + 3];
        *(float4*)(g_seqout + t * 64 + tidj * 4) = v;
    }
}

// ---------------- stats for pn over seqout ----------------
__global__ __launch_bounds__(256) void k_stats3() {
    int tid = threadIdx.x;
    size_t base = (size_t)blockIdx.x * 16384;
    float s = 0.f, q = 0.f;
    for (int i = tid; i < 16384; i += 256) {
        float v = g_seqout[base + i];
        s += v; q += v * v;
    }
    int c = tid & 63, grp = tid >> 6;
    __shared__ float rs[4][64], rq[4][64];
    rs[grp][c] = s; rq[grp][c] = q;
    __syncthreads();
    if (tid < 64) {
        double S = 0.0, Q = 0.0;
#pragma unroll
        for (int g2 = 0; g2 < 4; g2++) { S += rs[g2][tid]; Q += rq[g2][tid]; }
        atomicAdd(&g_dsum[3][tid], S);
        atomicAdd(&g_dsq[3][tid], Q);
    }
}

// ---------------- final: transpose + pn + residual ----------------
__global__ __launch_bounds__(256) void k_final(const float* __restrict__ gg,
                                               const float* __restrict__ bb,
                                               float* __restrict__ out) {
    int z = blockIdx.y, n0 = blockIdx.x * 32, tid = threadIdx.x;
    __shared__ float sm[64][33];
    for (int idx = tid; idx < 2048; idx += 256) {
        int nn = idx >> 6, c = idx & 63;
        sm[c][nn] = g_seqout[((size_t)(n0 + nn) * ZD + z) * 64 + c];
    }
    __syncthreads();
    for (int idx = tid; idx < 2048; idx += 256) {
        int c = idx >> 5, nn = idx & 31;
        float scale = g_istd[3][c] * gg[c];
        float shift = bb[c] - g_mean[3][c] * scale;
        size_t off = ((size_t)c * ZD + z) * HW + n0 + nn;
        out[off] = g_h[off] + fmaf(sm[c][nn], scale, shift);
    }
}

// ---------------- launch ----------------
extern "C" void kernel_launch(void* const* d_in, const int* in_sizes, int n_in,
                              void* d_out, int out_size) {
    const float* x        = (const float*)d_in[0];
    const float* c1_w     = (const float*)d_in[1];
    const float* in1_g    = (const float*)d_in[2];
    const float* in1_b    = (const float*)d_in[3];
    const float* c2_w     = (const float*)d_in[4];
    const float* in2_g    = (const float*)d_in[5];
    const float* in2_b    = (const float*)d_in[6];
    const float* dw_w     = (const float*)d_in[7];
    const float* pw_w     = (const float*)d_in[8];
    const float* inr_g    = (const float*)d_in[9];
    const float* inr_b    = (const float*)d_in[10];
    const float* ln_g     = (const float*)d_in[11];
    const float* ln_b     = (const float*)d_in[12];
    const float* in_proj_w= (const float*)d_in[13];
    const float* conv1d_w = (const float*)d_in[14];
    const float* conv1d_b = (const float*)d_in[15];
    const float* x_proj_w = (const float*)d_in[16];
    const float* dt_proj_w= (const float*)d_in[17];
    const float* dt_proj_b= (const float*)d_in[18];
    const float* A_log    = (const float*)d_in[19];
    const float* D_p      = (const float*)d_in[20];
    const float* out_proj_w=(const float*)d_in[21];
    const float* proj_w   = (const float*)d_in[22];
    const float* proj_b   = (const float*)d_in[23];
    const float* pn_g     = (const float*)d_in[24];
    const float* pn_b     = (const float*)d_in[25];
    float* out = (float*)d_out;

    dim3 b256(256), b2d(16, 16);

    k_zero<<<1, 256>>>();
    k_prepA<<<8, 256>>>(A_log);
    k_conv1<<<dim3(4, Z1, CC), b2d>>>(x, c1_w);
    k_fin<<<1, 64>>>(0);
    k_conv2<<<dim3(4, Z2, CC), b2d>>>(c2_w, in1_g, in1_b);
    k_fin<<<1, 64>>>(1);
    k_h<<<8192, 256>>>(in2_g, in2_b);
    k_dw<<<dim3(4, ZD, CC), b2d>>>(dw_w);
    k_pw<<<512, 256>>>(pw_w);
    k_statsR<<<dim3(64, 4), 256>>>();
    k_fin<<<1, 64>>>(2);
    k_x2t<<<dim3(128, ZD), 256>>>(inr_g, inr_b);
    k_inproj<<<NTOK / 64, 256>>>(in_proj_w, ln_g, ln_b);
    k_conv1d<<<4096, 128>>>(conv1d_w, conv1d_b);
    k_xproj<<<NTOK / 16, 576>>>(x_proj_w);
    k_scan<<<4096, 128>>>(dt_proj_w, dt_proj_b, D_p);
    k_wc<<<1, 256>>>(out_proj_w, proj_w);
    k_outproj<<<NTOK / 64, 256>>>(proj_b);
    k_stats3<<<512, 256>>>();
    k_fin<<<1, 64>>>(3);
    k_final<<<dim3(128, ZD), 256>>>(pn_g, pn_b, out);
}

// round 5
// speedup vs baseline: 2.0265x; 2.0265x over previous
#include <cuda_runtime.h>
#include <cuda_bf16.h>
#include <math.h>

#define ZD   32
#define HH   64
#define WW   64
#define HW   4096
#define CIN  32
#define CC   64
#define Z1   33
#define Z2   34
#define DI   128
#define NTOK 131072
#define DST  16
#define EPSF 1e-5f

// ---------------- scratch ----------------
__device__ float g_buf1[CC * Z1 * HW];
__device__ float g_hn  [CC * Z1 * HW];
__device__ float g_buf2[CC * Z2 * HW];
__device__ float g_h   [CC * ZD * HW];
__device__ float g_dw  [CC * ZD * HW];
__device__ float g_pw  [CC * ZD * HW];
__device__ float g_x2t [NTOK * CC];
__device__ float g_xin [NTOK * DI];
__device__ float g_zg  [NTOK * DI];
__device__ float g_xa  [NTOK * DI];
__device__ float g_xdbl[NTOK * 36];
__device__ float g_y   [NTOK * DI];
__device__ float g_seqout[NTOK * CC];
__device__ float g_A   [DI * DST];
__device__ float g_wc  [CC * DI];

__device__ double g_dsum[4][64];
__device__ double g_dsq [4][64];
__device__ float  g_mean[4][64];
__device__ float  g_istd[4][64];

// ---------------- helpers ----------------
__device__ __forceinline__ float fsilu(float x) {
    return x * (1.f / (1.f + __expf(-x)));
}
__device__ __forceinline__ float flrelu(float x) {
    return fmaxf(x, 0.01f * x);
}

__device__ __forceinline__ void stat_reduce_256(float s, float q, int tid,
                                                double* ds, double* dq) {
#pragma unroll
    for (int o = 16; o > 0; o >>= 1) {
        s += __shfl_down_sync(0xffffffffu, s, o);
        q += __shfl_down_sync(0xffffffffu, q, o);
    }
    __shared__ float shs[8], shq[8];
    if ((tid & 31) == 0) { shs[tid >> 5] = s; shq[tid >> 5] = q; }
    __syncthreads();
    if (tid == 0) {
        float S = 0.f, Q = 0.f;
#pragma unroll
        for (int i = 0; i < 8; i++) { S += shs[i]; Q += shq[i]; }
        atomicAdd(ds, (double)S);
        atomicAdd(dq, (double)Q);
    }
}

// ---------------- service ----------------
__global__ void k_zero() {
    int tid = threadIdx.x;
    if (tid < 256) {
        ((double*)g_dsum)[tid] = 0.0;
        ((double*)g_dsq)[tid]  = 0.0;
    }
}

__global__ void k_prepA(const float* __restrict__ A_log) {
    int i = blockIdx.x * blockDim.x + threadIdx.x;
    if (i < DI * DST) g_A[i] = -expf(A_log[i]);
}

__global__ void k_fin(int which) {
    int c = threadIdx.x;
    if (c >= 64) return;
    const double counts[4] = {33.0 * 4096.0, 34.0 * 4096.0, 131072.0, 131072.0};
    double n = counts[which];
    double m = g_dsum[which][c] / n;
    double v = g_dsq[which][c] / n - m * m;
    g_mean[which][c] = (float)m;
    g_istd[which][c] = (float)(1.0 / sqrt(v + 1e-5));
}

// per-co-group stats: 8 channels, acc[8][4]
template<int WHICH>
__device__ __forceinline__ void stats8(const float acc[8][4], int co0, int tid) {
    float s[8], q[8];
#pragma unroll
    for (int co = 0; co < 8; co++) {
        s[co] = acc[co][0] + acc[co][1] + acc[co][2] + acc[co][3];
        q[co] = acc[co][0] * acc[co][0] + acc[co][1] * acc[co][1] +
                acc[co][2] * acc[co][2] + acc[co][3] * acc[co][3];
    }
#pragma unroll
    for (int o = 16; o > 0; o >>= 1) {
#pragma unroll
        for (int co = 0; co < 8; co++) {
            s[co] += __shfl_down_sync(0xffffffffu, s[co], o);
            q[co] += __shfl_down_sync(0xffffffffu, q[co], o);
        }
    }
    __shared__ float rs[8][8], rq[8][8];
    int wid = tid >> 5, lane = tid & 31;
    if (lane == 0) {
#pragma unroll
        for (int co = 0; co < 8; co++) { rs[wid][co] = s[co]; rq[wid][co] = q[co]; }
    }
    __syncthreads();
    if (tid < 8) {
        float S = 0.f, Q = 0.f;
#pragma unroll
        for (int w = 0; w < 8; w++) { S += rs[w][tid]; Q += rq[w][tid]; }
        atomicAdd(&g_dsum[WHICH][co0 + tid], (double)S);
        atomicAdd(&g_dsq[WHICH][co0 + tid], (double)Q);
    }
}

// ---------------- conv1: 8 output channels per block ----------------
__global__ __launch_bounds__(256) void k_conv1(const float* __restrict__ x,
                                               const float* __restrict__ w) {
    const int tileR = blockIdx.x * 16;
    const int zo = blockIdx.y;
    const int co0 = blockIdx.z * 8;
    __shared__ float ws[8 * CIN * 18];                 // 4608
    __shared__ __align__(16) float ts[2][18 * 68];     // 2448
    const int tx = threadIdx.x, ty = threadIdx.y;
    const int tid = ty * 16 + tx;
    for (int i = tid; i < 8 * CIN * 18; i += 256) {
        int co = i / (CIN * 18), r = i - co * (CIN * 18);
        ws[co * (CIN * 18) + r] = w[(co0 + co) * (CIN * 18) + r];
    }
    float acc[8][4] = {};
    for (int ci = 0; ci < CIN; ci++) {
        __syncthreads();
        for (int kz = 0; kz < 2; kz++) {
            int zz = zo - 1 + kz;
            bool zok = (zz >= 0 && zz < ZD);
            const float* xp = x + ((size_t)ci * ZD + zz) * HW;
            for (int i = tid; i < 18 * 68; i += 256) {
                int r = i / 68, c2 = i - r * 68;
                int gr = tileR + r - 1, gc = c2 - 1;
                float v = 0.f;
                if (zok && gr >= 0 && gr < HH && gc >= 0 && gc < WW)
                    v = xp[gr * WW + gc];
                ts[kz][i] = v;
            }
        }
        __syncthreads();
#pragma unroll
        for (int kz = 0; kz < 2; kz++) {
#pragma unroll
            for (int ky = 0; ky < 3; ky++) {
                const float4* rp = (const float4*)(ts[kz] + (ty + ky) * 68 + (tx << 2));
                float4 va = rp[0], vb = rp[1];
                float v0 = va.x, v1 = va.y, v2 = va.z, v3 = va.w, v4 = vb.x, v5 = vb.y;
#pragma unroll
                for (int co = 0; co < 8; co++) {
                    const float* wp = ws + co * (CIN * 18) + ci * 18 + kz * 9 + ky * 3;
                    float w0 = wp[0], w1 = wp[1], w2 = wp[2];
                    acc[co][0] = fmaf(w0, v0, fmaf(w1, v1, fmaf(w2, v2, acc[co][0])));
                    acc[co][1] = fmaf(w0, v1, fmaf(w1, v2, fmaf(w2, v3, acc[co][1])));
                    acc[co][2] = fmaf(w0, v2, fmaf(w1, v3, fmaf(w2, v4, acc[co][2])));
                    acc[co][3] = fmaf(w0, v3, fmaf(w1, v4, fmaf(w2, v5, acc[co][3])));
                }
            }
        }
    }
    int gr = tileR + ty, gc0 = tx << 2;
#pragma unroll
    for (int co = 0; co < 8; co++) {
        *(float4*)(g_buf1 + ((size_t)(co0 + co) * Z1 + zo) * HW + gr * WW + gc0) =
            make_float4(acc[co][0], acc[co][1], acc[co][2], acc[co][3]);
    }
    __syncthreads();
    stats8<0>(acc, co0, tid);
}

// ---------------- hn = lrelu(inorm1(buf1)) ----------------
__global__ __launch_bounds__(256) void k_hn(const float* __restrict__ gg,
                                            const float* __restrict__ bb) {
    int base = (blockIdx.x * 256 + threadIdx.x) * 4;
    int c = base / (Z1 * HW);
    int off = base - c * (Z1 * HW);
    float scale = g_istd[0][c] * gg[c];
    float shift = bb[c] - g_mean[0][c] * scale;
    float4 r = *(const float4*)(g_buf1 + (size_t)c * (Z1 * HW) + off);
    float4 o;
    o.x = flrelu(fmaf(r.x, scale, shift));
    o.y = flrelu(fmaf(r.y, scale, shift));
    o.z = flrelu(fmaf(r.z, scale, shift));
    o.w = flrelu(fmaf(r.w, scale, shift));
    *(float4*)(g_hn + base) = o;
}

// ---------------- conv2: 8 output channels per block ----------------
__global__ __launch_bounds__(256) void k_conv2(const float* __restrict__ w) {
    const int tileR = blockIdx.x * 16;
    const int zo = blockIdx.y;
    const int co0 = blockIdx.z * 8;
    __shared__ float ws[8 * CC * 18];                  // 9216 floats
    __shared__ __align__(16) float ts[2][18 * 68];
    const int tx = threadIdx.x, ty = threadIdx.y;
    const int tid = ty * 16 + tx;
    for (int i = tid; i < 8 * CC * 18; i += 256) {
        int co = i / (CC * 18), r = i - co * (CC * 18);
        ws[co * (CC * 18) + r] = w[(co0 + co) * (CC * 18) + r];
    }
    float acc[8][4] = {};
    for (int ci = 0; ci < CC; ci++) {
        __syncthreads();
        for (int kz = 0; kz < 2; kz++) {
            int zz = zo - 1 + kz;
            bool zok = (zz >= 0 && zz < Z1);
            const float* xp = g_hn + ((size_t)ci * Z1 + zz) * HW;
            for (int i = tid; i < 18 * 68; i += 256) {
                int r = i / 68, c2 = i - r * 68;
                int gr = tileR + r - 1, gc = c2 - 1;
                float v = 0.f;
                if (zok && gr >= 0 && gr < HH && gc >= 0 && gc < WW)
                    v = xp[gr * WW + gc];
                ts[kz][i] = v;
            }
        }
        __syncthreads();
#pragma unroll
        for (int kz = 0; kz < 2; kz++) {
#pragma unroll
            for (int ky = 0; ky < 3; ky++) {
                const float4* rp = (const float4*)(ts[kz] + (ty + ky) * 68 + (tx << 2));
                float4 va = rp[0], vb = rp[1];
                float v0 = va.x, v1 = va.y, v2 = va.z, v3 = va.w, v4 = vb.x, v5 = vb.y;
#pragma unroll
                for (int co = 0; co < 8; co++) {
                    const float* wp = ws + co * (CC * 18) + ci * 18 + kz * 9 + ky * 3;
                    float w0 = wp[0], w1 = wp[1], w2 = wp[2];
                    acc[co][0] = fmaf(w0, v0, fmaf(w1, v1, fmaf(w2, v2, acc[co][0])));
                    acc[co][1] = fmaf(w0, v1, fmaf(w1, v2, fmaf(w2, v3, acc[co][1])));
                    acc[co][2] = fmaf(w0, v2, fmaf(w1, v3, fmaf(w2, v4, acc[co][2])));
                    acc[co][3] = fmaf(w0, v3, fmaf(w1, v4, fmaf(w2, v5, acc[co][3])));
                }
            }
        }
    }
    int gr = tileR + ty, gc0 = tx << 2;
#pragma unroll
    for (int co = 0; co < 8; co++) {
        *(float4*)(g_buf2 + ((size_t)(co0 + co) * Z2 + zo) * HW + gr * WW + gc0) =
            make_float4(acc[co][0], acc[co][1], acc[co][2], acc[co][3]);
    }
    __syncthreads();
    stats8<1>(acc, co0, tid);
}

// ---------------- h = lrelu(inorm2(buf2[:, :32])) ----------------
__global__ __launch_bounds__(256) void k_h(const float* __restrict__ gg,
                                           const float* __restrict__ bb) {
    int base = (blockIdx.x * 256 + threadIdx.x) * 4;
    int c = base >> 17;
    int off = base & 131071;
    float scale = g_istd[1][c] * gg[c];
    float shift = bb[c] - g_mean[1][c] * scale;
    float4 r = *(const float4*)(g_buf2 + (size_t)c * (Z2 * HW) + off);
    float4 o;
    o.x = flrelu(fmaf(r.x, scale, shift));
    o.y = flrelu(fmaf(r.y, scale, shift));
    o.z = flrelu(fmaf(r.z, scale, shift));
    o.w = flrelu(fmaf(r.w, scale, shift));
    *(float4*)(g_h + base) = o;
}

// ---------------- depthwise 3x3 spatial ----------------
__global__ __launch_bounds__(256) void k_dw(const float* __restrict__ w) {
    const int tileR = blockIdx.x * 16;
    const int z = blockIdx.y;
    const int c = blockIdx.z;
    __shared__ __align__(16) float ins[18 * 68];
    const int tx = threadIdx.x, ty = threadIdx.y;
    const int tid = ty * 16 + tx;
    float wv[9];
#pragma unroll
    for (int i = 0; i < 9; i++) wv[i] = __ldg(w + c * 9 + i);
    const float* xp = g_h + ((size_t)c * ZD + z) * HW;
    for (int i = tid; i < 18 * 68; i += 256) {
        int r = i / 68, c2 = i - r * 68;
        int gr = tileR + r - 1, gc = c2 - 1;
        float v = 0.f;
        if (gr >= 0 && gr < HH && gc >= 0 && gc < WW) v = xp[gr * WW + gc];
        ins[i] = v;
    }
    __syncthreads();
    float a0 = 0.f, a1 = 0.f, a2 = 0.f, a3 = 0.f;
#pragma unroll
    for (int ky = 0; ky < 3; ky++) {
        const float4* rp = (const float4*)(ins + (ty + ky) * 68 + (tx << 2));
        float4 va = rp[0], vb = rp[1];
        float v0 = va.x, v1 = va.y, v2 = va.z, v3 = va.w, v4 = vb.x, v5 = vb.y;
        float w0 = wv[3 * ky], w1 = wv[3 * ky + 1], w2 = wv[3 * ky + 2];
        a0 = fmaf(w0, v0, fmaf(w1, v1, fmaf(w2, v2, a0)));
        a1 = fmaf(w0, v1, fmaf(w1, v2, fmaf(w2, v3, a1)));
        a2 = fmaf(w0, v2, fmaf(w1, v3, fmaf(w2, v4, a2)));
        a3 = fmaf(w0, v3, fmaf(w1, v4, fmaf(w2, v5, a3)));
    }
    int gr = tileR + ty, gc0 = tx << 2;
    *(float4*)(g_dw + ((size_t)c * ZD + z) * HW + gr * WW + gc0) =
        make_float4(a0, a1, a2, a3);
}

// ---------------- pointwise 64x64 (weights transposed, vector LDS) ----------------
__global__ __launch_bounds__(256) void k_pw(const float* __restrict__ w) {
    __shared__ __align__(16) float wsm[64 * 64];      // [ci][co]
    int tid = threadIdx.x;
    for (int idx = tid; idx < 4096; idx += 256) {
        int ci = idx >> 6, co = idx & 63;
        wsm[idx] = w[co * 64 + ci];
    }
    __syncthreads();
    int p = blockIdx.x * 256 + tid;
    float acc[64];
#pragma unroll
    for (int co = 0; co < 64; co++) acc[co] = 0.f;
    for (int ci = 0; ci < 64; ci++) {
        float v = g_dw[(size_t)ci * (ZD * HW) + p];
        const float4* wr = (const float4*)(wsm + ci * 64);
#pragma unroll
        for (int c4 = 0; c4 < 16; c4++) {
            float4 wv = wr[c4];
            acc[c4 * 4 + 0] = fmaf(wv.x, v, acc[c4 * 4 + 0]);
            acc[c4 * 4 + 1] = fmaf(wv.y, v, acc[c4 * 4 + 1]);
            acc[c4 * 4 + 2] = fmaf(wv.z, v, acc[c4 * 4 + 2]);
            acc[c4 * 4 + 3] = fmaf(wv.w, v, acc[c4 * 4 + 3]);
        }
    }
#pragma unroll
    for (int co = 0; co < 64; co++) g_pw[(size_t)co * (ZD * HW) + p] = acc[co];
}

// ---------------- stats for inorm_r ----------------
__global__ __launch_bounds__(256) void k_statsR() {
    int c = blockIdx.x;
    int tid = threadIdx.x;
    size_t base = (size_t)c * (ZD * HW) + (size_t)blockIdx.y * 32768;
    float s = 0.f, q = 0.f;
    for (int i = tid; i < 32768; i += 256) {
        float v = g_pw[base + i];
        s += v; q += v * v;
    }
    stat_reduce_256(s, q, tid, &g_dsum[2][c], &g_dsq[2][c]);
}

// ---------------- x2 + transpose to token layout ----------------
__global__ __launch_bounds__(256) void k_x2t(const float* __restrict__ gg,
                                             const float* __restrict__ bb) {
    int z = blockIdx.y, n0 = blockIdx.x * 32, tid = threadIdx.x;
    __shared__ float sm[64][33];
    for (int idx = tid; idx < 2048; idx += 256) {
        int c = idx >> 5, nn = idx & 31;
        size_t off = (size_t)c * (ZD * HW) + (size_t)z * HW + n0 + nn;
        float scale = g_istd[2][c] * gg[c];
        float shift = bb[c] - g_mean[2][c] * scale;
        float v = fmaf(g_pw[off], scale, shift);
        sm[c][nn] = g_h[off] + fsilu(v);
    }
    __syncthreads();
    for (int idx = tid; idx < 2048; idx += 256) {
        int nn = idx >> 6, c = idx & 63;
        size_t t = (size_t)(n0 + nn) * ZD + z;
        g_x2t[t * 64 + c] = sm[c][nn];
    }
}

// ---------------- LN + in_proj (vectorized) ----------------
__global__ __launch_bounds__(256) void k_inproj(const float* __restrict__ W,
                                                const float* __restrict__ lg,
                                                const float* __restrict__ lb) {
    __shared__ __align__(16) float tok[64][68];
    __shared__ __align__(16) float wsm[64][68];
    int tid = threadIdx.x;
    int t0 = blockIdx.x * 64;
    int wi = tid >> 5, lane = tid & 31;
    float g0 = lg[lane], g1 = lg[lane + 32], b0 = lb[lane], b1 = lb[lane + 32];
    for (int tt = wi; tt < 64; tt += 8) {
        int t = t0 + tt;
        float v0 = g_x2t[(size_t)t * 64 + lane];
        float v1 = g_x2t[(size_t)t * 64 + lane + 32];
        float s = v0 + v1, q = v0 * v0 + v1 * v1;
#pragma unroll
        for (int o = 16; o > 0; o >>= 1) {
            s += __shfl_xor_sync(0xffffffffu, s, o);
            q += __shfl_xor_sync(0xffffffffu, q, o);
        }
        float mean = s * (1.f / 64.f);
        float var = q * (1.f / 64.f) - mean * mean;
        float istd = rsqrtf(var + EPSF);
        tok[tt][lane]      = (v0 - mean) * istd * g0 + b0;
        tok[tt][lane + 32] = (v1 - mean) * istd * g1 + b1;
    }
    int tidt = tid >> 4, tidj = tid & 15;
    for (int jc = 0; jc < 4; jc++) {
        __syncthreads();
        for (int idx = tid; idx < 4096; idx += 256) {
            int jr = idx >> 6, c = idx & 63;
            wsm[jr][c] = W[(jc * 64 + jr) * 64 + c];
        }
        __syncthreads();
        float acc[4][4] = {};
#pragma unroll
        for (int c4 = 0; c4 < 16; c4++) {
            float4 a[4], wv[4];
#pragma unroll
            for (int i = 0; i < 4; i++) a[i] = *(const float4*)&tok[tidt * 4 + i][c4 * 4];
#pragma unroll
            for (int j = 0; j < 4; j++) wv[j] = *(const float4*)&wsm[tidj * 4 + j][c4 * 4];
#pragma unroll
            for (int i = 0; i < 4; i++)
#pragma unroll
                for (int j = 0; j < 4; j++) {
                    acc[i][j] = fmaf(a[i].x, wv[j].x, acc[i][j]);
                    acc[i][j] = fmaf(a[i].y, wv[j].y, acc[i][j]);
                    acc[i][j] = fmaf(a[i].z, wv[j].z, acc[i][j]);
                    acc[i][j] = fmaf(a[i].w, wv[j].w, acc[i][j]);
                }
        }
#pragma unroll
        for (int i = 0; i < 4; i++) {
            size_t t = t0 + tidt * 4 + i;
            float4 v = make_float4(acc[i][0], acc[i][1], acc[i][2], acc[i][3]);
            if (jc < 2) *(float4*)(g_xin + t * 128 + jc * 64 + tidj * 4) = v;
            else        *(float4*)(g_zg  + t * 128 + (jc - 2) * 64 + tidj * 4) = v;
        }
    }
}

// ---------------- causal conv1d + silu (smem staged) ----------------
__global__ __launch_bounds__(128) void k_conv1d(const float* __restrict__ w,
                                                const float* __restrict__ b) {
    int n = blockIdx.x, d = threadIdx.x;
    __shared__ float sx[4096];
    size_t nb = (size_t)n * 4096;
    for (int i = d; i < 4096; i += 128) sx[i] = g_xin[nb + i];
    __syncthreads();
    float4 wv = ((const float4*)w)[d];
    float bias = b[d];
    float x0 = 0.f, x1 = 0.f, x2v = 0.f;
#pragma unroll 4
    for (int z = 0; z < ZD; z++) {
        float xn = sx[z * 128 + d];
        float v = fmaf(wv.x, x0, fmaf(wv.y, x1, fmaf(wv.z, x2v, fmaf(wv.w, xn, bias))));
        g_xa[nb + z * 128 + d] = fsilu(v);
        x0 = x1; x1 = x2v; x2v = xn;
    }
}

// ---------------- x_proj (vectorized) ----------------
__global__ __launch_bounds__(576) void k_xproj(const float* __restrict__ W) {
    __shared__ __align__(16) float xs[16][132];
    __shared__ __align__(16) float wx[36][132];
    int tid = threadIdx.x;
    int t0 = blockIdx.x * 16;
    for (int idx = tid; idx < 16 * 128; idx += 576) {
        int r = idx >> 7, dd = idx & 127;
        xs[r][dd] = g_xa[(size_t)(t0 + r) * DI + dd];
    }
    for (int idx = tid; idx < 36 * 128; idx += 576) {
        int j = idx >> 7, dd = idx & 127;
        wx[j][dd] = W[idx];
    }
    __syncthreads();
    int j = tid % 36, tl = tid / 36;
    float acc = 0.f;
#pragma unroll
    for (int d4 = 0; d4 < 32; d4++) {
        float4 xa = *(const float4*)&xs[tl][d4 * 4];
        float4 wv = *(const float4*)&wx[j][d4 * 4];
        acc = fmaf(xa.x, wv.x, acc);
        acc = fmaf(xa.y, wv.y, acc);
        acc = fmaf(xa.z, wv.z, acc);
        acc = fmaf(xa.w, wv.w, acc);
    }
    g_xdbl[(size_t)(t0 + tl) * 36 + j] = acc;
}

// ---------------- dt + selective scan + gate (smem staged) ----------------
__global__ __launch_bounds__(128) void k_scan(const float* __restrict__ dtw,
                                              const float* __restrict__ dtb,
                                              const float* __restrict__ Dp_) {
    int n = blockIdx.x, d = threadIdx.x;
    __shared__ __align__(16) float sxd[1152];
    __shared__ float su[4096], szg[4096];
    size_t nb = (size_t)n * 4096;
    for (int i = d; i < 1152; i += 128) sxd[i] = g_xdbl[(size_t)n * 1152 + i];
    for (int i = d; i < 4096; i += 128) {
        su[i] = g_xa[nb + i];
        szg[i] = g_zg[nb + i];
    }
    __syncthreads();
    float4 wdt = ((const float4*)dtw)[d];
    float bdt = dtb[d], Dp = Dp_[d];
    float A[DST];
    bool fast = true;
#pragma unroll
    for (int s = 0; s < DST; s++) {
        A[s] = g_A[d * DST + s];
        fast = fast && (fabsf(A[s] + (float)(s + 1)) <= 2e-6f * (float)(s + 1));
    }
    float st[DST];
#pragma unroll
    for (int s = 0; s < DST; s++) st[s] = 0.f;
    for (int z = 0; z < ZD; z++) {
        const float* xz = sxd + z * 36;
        float4 h0 = *(const float4*)xz;
        float4 b4[4], c4v[4];
#pragma unroll
        for (int k = 0; k < 4; k++) {
            b4[k]  = *(const float4*)(xz + 4 + 4 * k);
            c4v[k] = *(const float4*)(xz + 20 + 4 * k);
        }
        float Bv[16] = {b4[0].x, b4[0].y, b4[0].z, b4[0].w,
                        b4[1].x, b4[1].y, b4[1].z, b4[1].w,
                        b4[2].x, b4[2].y, b4[2].z, b4[2].w,
                        b4[3].x, b4[3].y, b4[3].z, b4[3].w};
        float Cv[16] = {c4v[0].x, c4v[0].y, c4v[0].z, c4v[0].w,
                        c4v[1].x, c4v[1].y, c4v[1].z, c4v[1].w,
                        c4v[2].x, c4v[2].y, c4v[2].z, c4v[2].w,
                        c4v[3].x, c4v[3].y, c4v[3].z, c4v[3].w};
        float pre = fmaf(wdt.x, h0.x, fmaf(wdt.y, h0.y,
                    fmaf(wdt.z, h0.z, fmaf(wdt.w, h0.w, bdt))));
        float dt = (pre > 15.f) ? pre : log1pf(__expf(pre));
        float u = su[z * 128 + d];
        float du = dt * u;
        float y = 0.f;
        if (fast) {
            float E = __expf(-dt);
            float ep = E;
#pragma unroll
            for (int s = 0; s < DST; s++) {
                st[s] = fmaf(ep, st[s], du * Bv[s]);
                y = fmaf(st[s], Cv[s], y);
                ep *= E;
            }
        } else {
#pragma unroll
            for (int s = 0; s < DST; s++) {
                float e = __expf(dt * A[s]);
                st[s] = fmaf(e, st[s], du * Bv[s]);
                y = fmaf(st[s], Cv[s], y);
            }
        }
        float zg = szg[z * 128 + d];
        g_y[nb + z * 128 + d] = fmaf(Dp, u, y) * fsilu(zg);
    }
}

// ---------------- Wc = proj_w @ out_proj_w ----------------
__global__ __launch_bounds__(256) void k_wc(const float* __restrict__ op,
                                            const float* __restrict__ pj) {
    int idx = blockIdx.x * 256 + threadIdx.x;
    if (idx >= 64 * 128) return;
    int o = idx >> 7, dd = idx & 127;
    float acc = 0.f;
#pragma unroll 8
    for (int c = 0; c < 64; c++)
        acc = fmaf(pj[o * 64 + c], op[c * 128 + dd], acc);
    g_wc[idx] = acc;
}

// ---------------- seqout = y @ Wc^T + proj_b (vectorized) ----------------
__global__ __launch_bounds__(256) void k_outproj(const float* __restrict__ pb) {
    __shared__ __align__(16) float tok[64][68];
    __shared__ __align__(16) float wsm[64][68];
    int tid = threadIdx.x;
    int t0 = blockIdx.x * 64;
    int tidt = tid >> 4, tidj = tid & 15;
    float acc[4][4] = {};
    for (int kc = 0; kc < 2; kc++) {
        __syncthreads();
        for (int idx = tid; idx < 4096; idx += 256) {
            int r = idx >> 6, k = idx & 63;
            tok[r][k] = g_y[(size_t)(t0 + r) * DI + kc * 64 + k];
            wsm[r][k] = g_wc[r * DI + kc * 64 + k];
        }
        __syncthreads();
#pragma unroll
        for (int c4 = 0; c4 < 16; c4++) {
            float4 a[4], wv[4];
#pragma unroll
            for (int i = 0; i < 4; i++) a[i] = *(const float4*)&tok[tidt * 4 + i][c4 * 4];
#pragma unroll
            for (int j = 0; j < 4; j++) wv[j] = *(const float4*)&wsm[tidj * 4 + j][c4 * 4];
#pragma unroll
            for (int i = 0; i < 4; i++)
#pragma unroll
                for (int j = 0; j < 4; j++) {
                    acc[i][j] = fmaf(a[i].x, wv[j].x, acc[i][j]);
                    acc[i][j] = fmaf(a[i].y, wv[j].y, acc[i][j]);
                    acc[i][j] = fmaf(a[i].z, wv[j].z, acc[i][j]);
                    acc[i][j] = fmaf(a[i].w, wv[j].w, acc[i][j]);
                }
        }
    }
#pragma unroll
    for (int i = 0; i < 4; i++) {
        size_t t = t0 + tidt * 4 + i;
        float4 v;
        v.x = acc[i][0] + pb[tidj * 4 + 0];
        v.y = acc[i][1] + pb[tidj * 4 + 1];
        v.z = acc[i][2] + pb[tidj * 4 + 2];
        v.w = acc[i][3] + pb[tidj * 4 + 3];
        *(float4*)(g_seqout + t * 64 + tidj * 4) = v;
    }
}

// ---------------- stats for pn over seqout ----------------
__global__ __launch_bounds__(256) void k_stats3() {
    int tid = threadIdx.x;
    size_t base = (size_t)blockIdx.x * 16384;
    float s = 0.f, q = 0.f;
    for (int i = tid; i < 16384; i += 256) {
        float v = g_seqout[base + i];
        s += v; q += v * v;
    }
    int c = tid & 63, grp = tid >> 6;
    __shared__ float rs[4][64], rq[4][64];
    rs[grp][c] = s; rq[grp][c] = q;
    __syncthreads();
    if (tid < 64) {
        double S = 0.0, Q = 0.0;
#pragma unroll
        for (int g2 = 0; g2 < 4; g2++) { S += rs[g2][tid]; Q += rq[g2][tid]; }
        atomicAdd(&g_dsum[3][tid], S);
        atomicAdd(&g_dsq[3][tid], Q);
    }
}

// ---------------- final: transpose + pn + residual ----------------
__global__ __launch_bounds__(256) void k_final(const float* __restrict__ gg,
                                               const float* __restrict__ bb,
                                               float* __restrict__ out) {
    int z = blockIdx.y, n0 = blockIdx.x * 32, tid = threadIdx.x;
    __shared__ float sm[64][33];
    for (int idx = tid; idx < 2048; idx += 256) {
        int nn = idx >> 6, c = idx & 63;
        sm[c][nn] = g_seqout[((size_t)(n0 + nn) * ZD + z) * 64 + c];
    }
    __syncthreads();
    for (int idx = tid; idx < 2048; idx += 256) {
        int c = idx >> 5, nn = idx & 31;
        float scale = g_istd[3][c] * gg[c];
        float shift = bb[c] - g_mean[3][c] * scale;
        size_t off = ((size_t)c * ZD + z) * HW + n0 + nn;
        out[off] = g_h[off] + fmaf(sm[c][nn], scale, shift);
    }
}

// ---------------- launch ----------------
extern "C" void kernel_launch(void* const* d_in, const int* in_sizes, int n_in,
                              void* d_out, int out_size) {
    const float* x        = (const float*)d_in[0];
    const float* c1_w     = (const float*)d_in[1];
    const float* in1_g    = (const float*)d_in[2];
    const float* in1_b    = (const float*)d_in[3];
    const float* c2_w     = (const float*)d_in[4];
    const float* in2_g    = (const float*)d_in[5];
    const float* in2_b    = (const float*)d_in[6];
    const float* dw_w     = (const float*)d_in[7];
    const float* pw_w     = (const float*)d_in[8];
    const float* inr_g    = (const float*)d_in[9];
    const float* inr_b    = (const float*)d_in[10];
    const float* ln_g     = (const float*)d_in[11];
    const float* ln_b     = (const float*)d_in[12];
    const float* in_proj_w= (const float*)d_in[13];
    const float* conv1d_w = (const float*)d_in[14];
    const float* conv1d_b = (const float*)d_in[15];
    const float* x_proj_w = (const float*)d_in[16];
    const float* dt_proj_w= (const float*)d_in[17];
    const float* dt_proj_b= (const float*)d_in[18];
    const float* A_log    = (const float*)d_in[19];
    const float* D_p      = (const float*)d_in[20];
    const float* out_proj_w=(const float*)d_in[21];
    const float* proj_w   = (const float*)d_in[22];
    const float* proj_b   = (const float*)d_in[23];
    const float* pn_g     = (const float*)d_in[24];
    const float* pn_b     = (const float*)d_in[25];
    float* out = (float*)d_out;

    dim3 b2d(16, 16);

    k_zero<<<1, 256>>>();
    k_prepA<<<8, 256>>>(A_log);
    k_conv1<<<dim3(4, Z1, 8), b2d>>>(x, c1_w);
    k_fin<<<1, 64>>>(0);
    k_hn<<<(CC * Z1 * HW / 4) / 256, 256>>>(in1_g, in1_b);
    k_conv2<<<dim3(4, Z2, 8), b2d>>>(c2_w);
    k_fin<<<1, 64>>>(1);
    k_h<<<8192, 256>>>(in2_g, in2_b);
    k_dw<<<dim3(4, ZD, CC), b2d>>>(dw_w);
    k_pw<<<512, 256>>>(pw_w);
    k_statsR<<<dim3(64, 4), 256>>>();
    k_fin<<<1, 64>>>(2);
    k_x2t<<<dim3(128, ZD), 256>>>(inr_g, inr_b);
    k_inproj<<<NTOK / 64, 256>>>(in_proj_w, ln_g, ln_b);
    k_conv1d<<<4096, 128>>>(conv1d_w, conv1d_b);
    k_xproj<<<NTOK / 16, 576>>>(x_proj_w);
    k_scan<<<4096, 128>>>(dt_proj_w, dt_proj_b, D_p);
    k_wc<<<32, 256>>>(out_proj_w, proj_w);
    k_outproj<<<NTOK / 64, 256>>>(proj_b);
    k_stats3<<<512, 256>>>();
    k_fin<<<1, 64>>>(3);
    k_final<<<dim3(128, ZD), 256>>>(pn_g, pn_b, out);
}

// round 7
// speedup vs baseline: 2.1288x; 1.0504x over previous
#include <cuda_runtime.h>
#include <cuda_bf16.h>
#include <math.h>

#define ZD   32
#define HH   64
#define WW   64
#define HW   4096
#define CIN  32
#define CC   64
#define Z1   33
#define Z2   34
#define DI   128
#define NTOK 131072
#define DST  16
#define EPSF 1e-5f

// ---------------- scratch ----------------
__device__ float g_buf1[CC * Z1 * HW];
__device__ float g_hn  [CC * Z1 * HW];
__device__ float g_buf2[CC * Z2 * HW];
__device__ float g_h   [CC * ZD * HW];
__device__ float g_dw  [CC * ZD * HW];
__device__ float g_pw  [CC * ZD * HW];
__device__ float g_x2t [NTOK * CC];
__device__ float g_xin [NTOK * DI];
__device__ float g_zg  [NTOK * DI];
__device__ float g_xa  [NTOK * DI];
__device__ float g_xdbl[NTOK * 36];
__device__ float g_y   [NTOK * DI];
__device__ float g_seqout[NTOK * CC];
__device__ float g_A   [DI * DST];
__device__ float g_wc  [CC * DI];

__device__ double g_dsum[4][64];
__device__ double g_dsq [4][64];
__device__ float  g_mean[4][64];
__device__ float  g_istd[4][64];

// ---------------- helpers ----------------
__device__ __forceinline__ float fsilu(float x) {
    return x * (1.f / (1.f + __expf(-x)));
}
__device__ __forceinline__ float flrelu(float x) {
    return fmaxf(x, 0.01f * x);
}

__device__ __forceinline__ void stat_reduce_256(float s, float q, int tid,
                                                double* ds, double* dq) {
#pragma unroll
    for (int o = 16; o > 0; o >>= 1) {
        s += __shfl_down_sync(0xffffffffu, s, o);
        q += __shfl_down_sync(0xffffffffu, q, o);
    }
    __shared__ float shs[8], shq[8];
    if ((tid & 31) == 0) { shs[tid >> 5] = s; shq[tid >> 5] = q; }
    __syncthreads();
    if (tid == 0) {
        float S = 0.f, Q = 0.f;
#pragma unroll
        for (int i = 0; i < 8; i++) { S += shs[i]; Q += shq[i]; }
        atomicAdd(ds, (double)S);
        atomicAdd(dq, (double)Q);
    }
}

// ---------------- service ----------------
__global__ void k_zero() {
    int tid = threadIdx.x;
    if (tid < 256) {
        ((double*)g_dsum)[tid] = 0.0;
        ((double*)g_dsq)[tid]  = 0.0;
    }
}

__global__ void k_prepA(const float* __restrict__ A_log) {
    int i = blockIdx.x * blockDim.x + threadIdx.x;
    if (i < DI * DST) g_A[i] = -expf(A_log[i]);
}

__global__ void k_fin(int which) {
    int c = threadIdx.x;
    if (c >= 64) return;
    const double counts[4] = {33.0 * 4096.0, 34.0 * 4096.0, 131072.0, 131072.0};
    double n = counts[which];
    double m = g_dsum[which][c] / n;
    double v = g_dsq[which][c] / n - m * m;
    g_mean[which][c] = (float)m;
    g_istd[which][c] = (float)(1.0 / sqrt(v + 1e-5));
}

// per-co-group stats: 8 channels, acc[8][4]
template<int WHICH>
__device__ __forceinline__ void stats8(const float acc[8][4], int co0, int tid) {
    float s[8], q[8];
#pragma unroll
    for (int co = 0; co < 8; co++) {
        s[co] = acc[co][0] + acc[co][1] + acc[co][2] + acc[co][3];
        q[co] = acc[co][0] * acc[co][0] + acc[co][1] * acc[co][1] +
                acc[co][2] * acc[co][2] + acc[co][3] * acc[co][3];
    }
#pragma unroll
    for (int o = 16; o > 0; o >>= 1) {
#pragma unroll
        for (int co = 0; co < 8; co++) {
            s[co] += __shfl_down_sync(0xffffffffu, s[co], o);
            q[co] += __shfl_down_sync(0xffffffffu, q[co], o);
        }
    }
    __shared__ float rs[8][8], rq[8][8];
    int wid = tid >> 5, lane = tid & 31;
    if (lane == 0) {
#pragma unroll
        for (int co = 0; co < 8; co++) { rs[wid][co] = s[co]; rq[wid][co] = q[co]; }
    }
    __syncthreads();
    if (tid < 8) {
        float S = 0.f, Q = 0.f;
#pragma unroll
        for (int w = 0; w < 8; w++) { S += rs[w][tid]; Q += rq[w][tid]; }
        atomicAdd(&g_dsum[WHICH][co0 + tid], (double)S);
        atomicAdd(&g_dsq[WHICH][co0 + tid], (double)Q);
    }
}

// ---------------- conv1: 8 output channels per block ----------------
__global__ __launch_bounds__(256) void k_conv1(const float* __restrict__ x,
                                               const float* __restrict__ w) {
    const int tileR = blockIdx.x * 16;
    const int zo = blockIdx.y;
    const int co0 = blockIdx.z * 8;
    __shared__ float ws[8 * CIN * 18];                 // 4608
    __shared__ __align__(16) float ts[2][18 * 68];     // 2448
    const int tx = threadIdx.x, ty = threadIdx.y;
    const int tid = ty * 16 + tx;
    for (int i = tid; i < 8 * CIN * 18; i += 256) {
        int co = i / (CIN * 18), r = i - co * (CIN * 18);
        ws[co * (CIN * 18) + r] = w[(co0 + co) * (CIN * 18) + r];
    }
    float acc[8][4] = {};
    for (int ci = 0; ci < CIN; ci++) {
        __syncthreads();
        for (int kz = 0; kz < 2; kz++) {
            int zz = zo - 1 + kz;
            bool zok = (zz >= 0 && zz < ZD);
            const float* xp = x + ((size_t)ci * ZD + zz) * HW;
            for (int i = tid; i < 18 * 68; i += 256) {
                int r = i / 68, c2 = i - r * 68;
                int gr = tileR + r - 1, gc = c2 - 1;
                float v = 0.f;
                if (zok && gr >= 0 && gr < HH && gc >= 0 && gc < WW)
                    v = xp[gr * WW + gc];
                ts[kz][i] = v;
            }
        }
        __syncthreads();
#pragma unroll
        for (int kz = 0; kz < 2; kz++) {
#pragma unroll
            for (int ky = 0; ky < 3; ky++) {
                const float4* rp = (const float4*)(ts[kz] + (ty + ky) * 68 + (tx << 2));
                float4 va = rp[0], vb = rp[1];
                float v0 = va.x, v1 = va.y, v2 = va.z, v3 = va.w, v4 = vb.x, v5 = vb.y;
#pragma unroll
                for (int co = 0; co < 8; co++) {
                    const float* wp = ws + co * (CIN * 18) + ci * 18 + kz * 9 + ky * 3;
                    float w0 = wp[0], w1 = wp[1], w2 = wp[2];
                    acc[co][0] = fmaf(w0, v0, fmaf(w1, v1, fmaf(w2, v2, acc[co][0])));
                    acc[co][1] = fmaf(w0, v1, fmaf(w1, v2, fmaf(w2, v3, acc[co][1])));
                    acc[co][2] = fmaf(w0, v2, fmaf(w1, v3, fmaf(w2, v4, acc[co][2])));
                    acc[co][3] = fmaf(w0, v3, fmaf(w1, v4, fmaf(w2, v5, acc[co][3])));
                }
            }
        }
    }
    int gr = tileR + ty, gc0 = tx << 2;
#pragma unroll
    for (int co = 0; co < 8; co++) {
        *(float4*)(g_buf1 + ((size_t)(co0 + co) * Z1 + zo) * HW + gr * WW + gc0) =
            make_float4(acc[co][0], acc[co][1], acc[co][2], acc[co][3]);
    }
    __syncthreads();
    stats8<0>(acc, co0, tid);
}

// ---------------- hn = lrelu(inorm1(buf1)) ----------------
__global__ __launch_bounds__(256) void k_hn(const float* __restrict__ gg,
                                            const float* __restrict__ bb) {
    int base = (blockIdx.x * 256 + threadIdx.x) * 4;
    int c = base / (Z1 * HW);
    int off = base - c * (Z1 * HW);
    float scale = g_istd[0][c] * gg[c];
    float shift = bb[c] - g_mean[0][c] * scale;
    float4 r = *(const float4*)(g_buf1 + (size_t)c * (Z1 * HW) + off);
    float4 o;
    o.x = flrelu(fmaf(r.x, scale, shift));
    o.y = flrelu(fmaf(r.y, scale, shift));
    o.z = flrelu(fmaf(r.z, scale, shift));
    o.w = flrelu(fmaf(r.w, scale, shift));
    *(float4*)(g_hn + base) = o;
}

// ---------------- conv2: 8 output channels per block ----------------
__global__ __launch_bounds__(256) void k_conv2(const float* __restrict__ w) {
    const int tileR = blockIdx.x * 16;
    const int zo = blockIdx.y;
    const int co0 = blockIdx.z * 8;
    __shared__ float ws[8 * CC * 18];                  // 9216 floats
    __shared__ __align__(16) float ts[2][18 * 68];
    const int tx = threadIdx.x, ty = threadIdx.y;
    const int tid = ty * 16 + tx;
    for (int i = tid; i < 8 * CC * 18; i += 256) {
        int co = i / (CC * 18), r = i - co * (CC * 18);
        ws[co * (CC * 18) + r] = w[(co0 + co) * (CC * 18) + r];
    }
    float acc[8][4] = {};
    for (int ci = 0; ci < CC; ci++) {
        __syncthreads();
        for (int kz = 0; kz < 2; kz++) {
            int zz = zo - 1 + kz;
            bool zok = (zz >= 0 && zz < Z1);
            const float* xp = g_hn + ((size_t)ci * Z1 + zz) * HW;
            for (int i = tid; i < 18 * 68; i += 256) {
                int r = i / 68, c2 = i - r * 68;
                int gr = tileR + r - 1, gc = c2 - 1;
                float v = 0.f;
                if (zok && gr >= 0 && gr < HH && gc >= 0 && gc < WW)
                    v = xp[gr * WW + gc];
                ts[kz][i] = v;
            }
        }
        __syncthreads();
#pragma unroll
        for (int kz = 0; kz < 2; kz++) {
#pragma unroll
            for (int ky = 0; ky < 3; ky++) {
                const float4* rp = (const float4*)(ts[kz] + (ty + ky) * 68 + (tx << 2));
                float4 va = rp[0], vb = rp[1];
                float v0 = va.x, v1 = va.y, v2 = va.z, v3 = va.w, v4 = vb.x, v5 = vb.y;
#pragma unroll
                for (int co = 0; co < 8; co++) {
                    const float* wp = ws + co * (CC * 18) + ci * 18 + kz * 9 + ky * 3;
                    float w0 = wp[0], w1 = wp[1], w2 = wp[2];
                    acc[co][0] = fmaf(w0, v0, fmaf(w1, v1, fmaf(w2, v2, acc[co][0])));
                    acc[co][1] = fmaf(w0, v1, fmaf(w1, v2, fmaf(w2, v3, acc[co][1])));
                    acc[co][2] = fmaf(w0, v2, fmaf(w1, v3, fmaf(w2, v4, acc[co][2])));
                    acc[co][3] = fmaf(w0, v3, fmaf(w1, v4, fmaf(w2, v5, acc[co][3])));
                }
            }
        }
    }
    int gr = tileR + ty, gc0 = tx << 2;
#pragma unroll
    for (int co = 0; co < 8; co++) {
        *(float4*)(g_buf2 + ((size_t)(co0 + co) * Z2 + zo) * HW + gr * WW + gc0) =
            make_float4(acc[co][0], acc[co][1], acc[co][2], acc[co][3]);
    }
    __syncthreads();
    stats8<1>(acc, co0, tid);
}

// ---------------- h = lrelu(inorm2(buf2[:, :32])) ----------------
__global__ __launch_bounds__(256) void k_h(const float* __restrict__ gg,
                                           const float* __restrict__ bb) {
    int base = (blockIdx.x * 256 + threadIdx.x) * 4;
    int c = base >> 17;
    int off = base & 131071;
    float scale = g_istd[1][c] * gg[c];
    float shift = bb[c] - g_mean[1][c] * scale;
    float4 r = *(const float4*)(g_buf2 + (size_t)c * (Z2 * HW) + off);
    float4 o;
    o.x = flrelu(fmaf(r.x, scale, shift));
    o.y = flrelu(fmaf(r.y, scale, shift));
    o.z = flrelu(fmaf(r.z, scale, shift));
    o.w = flrelu(fmaf(r.w, scale, shift));
    *(float4*)(g_h + base) = o;
}

// ---------------- depthwise 3x3 spatial ----------------
__global__ __launch_bounds__(256) void k_dw(const float* __restrict__ w) {
    const int tileR = blockIdx.x * 16;
    const int z = blockIdx.y;
    const int c = blockIdx.z;
    __shared__ __align__(16) float ins[18 * 68];
    const int tx = threadIdx.x, ty = threadIdx.y;
    const int tid = ty * 16 + tx;
    float wv[9];
#pragma unroll
    for (int i = 0; i < 9; i++) wv[i] = __ldg(w + c * 9 + i);
    const float* xp = g_h + ((size_t)c * ZD + z) * HW;
    for (int i = tid; i < 18 * 68; i += 256) {
        int r = i / 68, c2 = i - r * 68;
        int gr = tileR + r - 1, gc = c2 - 1;
        float v = 0.f;
        if (gr >= 0 && gr < HH && gc >= 0 && gc < WW) v = xp[gr * WW + gc];
        ins[i] = v;
    }
    __syncthreads();
    float a0 = 0.f, a1 = 0.f, a2 = 0.f, a3 = 0.f;
#pragma unroll
    for (int ky = 0; ky < 3; ky++) {
        const float4* rp = (const float4*)(ins + (ty + ky) * 68 + (tx << 2));
        float4 va = rp[0], vb = rp[1];
        float v0 = va.x, v1 = va.y, v2 = va.z, v3 = va.w, v4 = vb.x, v5 = vb.y;
        float w0 = wv[3 * ky], w1 = wv[3 * ky + 1], w2 = wv[3 * ky + 2];
        a0 = fmaf(w0, v0, fmaf(w1, v1, fmaf(w2, v2, a0)));
        a1 = fmaf(w0, v1, fmaf(w1, v2, fmaf(w2, v3, a1)));
        a2 = fmaf(w0, v2, fmaf(w1, v3, fmaf(w2, v4, a2)));
        a3 = fmaf(w0, v3, fmaf(w1, v4, fmaf(w2, v5, a3)));
    }
    int gr = tileR + ty, gc0 = tx << 2;
    *(float4*)(g_dw + ((size_t)c * ZD + z) * HW + gr * WW + gc0) =
        make_float4(a0, a1, a2, a3);
}

// ---------------- pointwise 64x64 (weights transposed, vector LDS) ----------------
__global__ __launch_bounds__(256) void k_pw(const float* __restrict__ w) {
    __shared__ __align__(16) float wsm[64 * 64];      // [ci][co]
    int tid = threadIdx.x;
    for (int idx = tid; idx < 4096; idx += 256) {
        int ci = idx >> 6, co = idx & 63;
        wsm[idx] = w[co * 64 + ci];
    }
    __syncthreads();
    int p = blockIdx.x * 256 + tid;
    float acc[64];
#pragma unroll
    for (int co = 0; co < 64; co++) acc[co] = 0.f;
    for (int ci = 0; ci < 64; ci++) {
        float v = g_dw[(size_t)ci * (ZD * HW) + p];
        const float4* wr = (const float4*)(wsm + ci * 64);
#pragma unroll
        for (int c4 = 0; c4 < 16; c4++) {
            float4 wv = wr[c4];
            acc[c4 * 4 + 0] = fmaf(wv.x, v, acc[c4 * 4 + 0]);
            acc[c4 * 4 + 1] = fmaf(wv.y, v, acc[c4 * 4 + 1]);
            acc[c4 * 4 + 2] = fmaf(wv.z, v, acc[c4 * 4 + 2]);
            acc[c4 * 4 + 3] = fmaf(wv.w, v, acc[c4 * 4 + 3]);
        }
    }
#pragma unroll
    for (int co = 0; co < 64; co++) g_pw[(size_t)co * (ZD * HW) + p] = acc[co];
}

// ---------------- stats for inorm_r ----------------
__global__ __launch_bounds__(256) void k_statsR() {
    int c = blockIdx.x;
    int tid = threadIdx.x;
    size_t base = (size_t)c * (ZD * HW) + (size_t)blockIdx.y * 32768;
    float s = 0.f, q = 0.f;
    for (int i = tid; i < 32768; i += 256) {
        float v = g_pw[base + i];
        s += v; q += v * v;
    }
    stat_reduce_256(s, q, tid, &g_dsum[2][c], &g_dsq[2][c]);
}

// ---------------- x2 + transpose to token layout ----------------
__global__ __launch_bounds__(256) void k_x2t(const float* __restrict__ gg,
                                             const float* __restrict__ bb) {
    int z = blockIdx.y, n0 = blockIdx.x * 32, tid = threadIdx.x;
    __shared__ float sm[64][33];
    for (int idx = tid; idx < 2048; idx += 256) {
        int c = idx >> 5, nn = idx & 31;
        size_t off = (size_t)c * (ZD * HW) + (size_t)z * HW + n0 + nn;
        float scale = g_istd[2][c] * gg[c];
        float shift = bb[c] - g_mean[2][c] * scale;
        float v = fmaf(g_pw[off], scale, shift);
        sm[c][nn] = g_h[off] + fsilu(v);
    }
    __syncthreads();
    for (int idx = tid; idx < 2048; idx += 256) {
        int nn = idx >> 6, c = idx & 63;
        size_t t = (size_t)(n0 + nn) * ZD + z;
        g_x2t[t * 64 + c] = sm[c][nn];
    }
}

// ---------------- LN + in_proj (vectorized) ----------------
__global__ __launch_bounds__(256) void k_inproj(const float* __restrict__ W,
                                                const float* __restrict__ lg,
                                                const float* __restrict__ lb) {
    __shared__ __align__(16) float tok[64][68];
    __shared__ __align__(16) float wsm[64][68];
    int tid = threadIdx.x;
    int t0 = blockIdx.x * 64;
    int wi = tid >> 5, lane = tid & 31;
    float g0 = lg[lane], g1 = lg[lane + 32], b0 = lb[lane], b1 = lb[lane + 32];
    for (int tt = wi; tt < 64; tt += 8) {
        int t = t0 + tt;
        float v0 = g_x2t[(size_t)t * 64 + lane];
        float v1 = g_x2t[(size_t)t * 64 + lane + 32];
        float s = v0 + v1, q = v0 * v0 + v1 * v1;
#pragma unroll
        for (int o = 16; o > 0; o >>= 1) {
            s += __shfl_xor_sync(0xffffffffu, s, o);
            q += __shfl_xor_sync(0xffffffffu, q, o);
        }
        float mean = s * (1.f / 64.f);
        float var = q * (1.f / 64.f) - mean * mean;
        float istd = rsqrtf(var + EPSF);
        tok[tt][lane]      = (v0 - mean) * istd * g0 + b0;
        tok[tt][lane + 32] = (v1 - mean) * istd * g1 + b1;
    }
    int tidt = tid >> 4, tidj = tid & 15;
    for (int jc = 0; jc < 4; jc++) {
        __syncthreads();
        for (int idx = tid; idx < 4096; idx += 256) {
            int jr = idx >> 6, c = idx & 63;
            wsm[jr][c] = W[(jc * 64 + jr) * 64 + c];
        }
        __syncthreads();
        float acc[4][4] = {};
#pragma unroll
        for (int c4 = 0; c4 < 16; c4++) {
            float4 a[4], wv[4];
#pragma unroll
            for (int i = 0; i < 4; i++) a[i] = *(const float4*)&tok[tidt * 4 + i][c4 * 4];
#pragma unroll
            for (int j = 0; j < 4; j++) wv[j] = *(const float4*)&wsm[tidj * 4 + j][c4 * 4];
#pragma unroll
            for (int i = 0; i < 4; i++)
#pragma unroll
                for (int j = 0; j < 4; j++) {
                    acc[i][j] = fmaf(a[i].x, wv[j].x, acc[i][j]);
                    acc[i][j] = fmaf(a[i].y, wv[j].y, acc[i][j]);
                    acc[i][j] = fmaf(a[i].z, wv[j].z, acc[i][j]);
                    acc[i][j] = fmaf(a[i].w, wv[j].w, acc[i][j]);
                }
        }
#pragma unroll
        for (int i = 0; i < 4; i++) {
            size_t t = t0 + tidt * 4 + i;
            float4 v = make_float4(acc[i][0], acc[i][1], acc[i][2], acc[i][3]);
            if (jc < 2) *(float4*)(g_xin + t * 128 + jc * 64 + tidj * 4) = v;
            else        *(float4*)(g_zg  + t * 128 + (jc - 2) * 64 + tidj * 4) = v;
        }
    }
}

// ---------------- causal conv1d + silu (smem staged) ----------------
__global__ __launch_bounds__(128) void k_conv1d(const float* __restrict__ w,
                                                const float* __restrict__ b) {
    int n = blockIdx.x, d = threadIdx.x;
    __shared__ float sx[4096];
    size_t nb = (size_t)n * 4096;
    for (int i = d; i < 4096; i += 128) sx[i] = g_xin[nb + i];
    __syncthreads();
    float4 wv = ((const float4*)w)[d];
    float bias = b[d];
    float x0 = 0.f, x1 = 0.f, x2v = 0.f;
#pragma unroll 4
    for (int z = 0; z < ZD; z++) {
        float xn = sx[z * 128 + d];
        float v = fmaf(wv.x, x0, fmaf(wv.y, x1, fmaf(wv.z, x2v, fmaf(wv.w, xn, bias))));
        g_xa[nb + z * 128 + d] = fsilu(v);
        x0 = x1; x1 = x2v; x2v = xn;
    }
}

// ---------------- x_proj (vectorized) ----------------
__global__ __launch_bounds__(576) void k_xproj(const float* __restrict__ W) {
    __shared__ __align__(16) float xs[16][132];
    __shared__ __align__(16) float wx[36][132];
    int tid = threadIdx.x;
    int t0 = blockIdx.x * 16;
    for (int idx = tid; idx < 16 * 128; idx += 576) {
        int r = idx >> 7, dd = idx & 127;
        xs[r][dd] = g_xa[(size_t)(t0 + r) * DI + dd];
    }
    for (int idx = tid; idx < 36 * 128; idx += 576) {
        int j = idx >> 7, dd = idx & 127;
        wx[j][dd] = W[idx];
    }
    __syncthreads();
    int j = tid % 36, tl = tid / 36;
    float acc = 0.f;
#pragma unroll
    for (int d4 = 0; d4 < 32; d4++) {
        float4 xa = *(const float4*)&xs[tl][d4 * 4];
        float4 wv = *(const float4*)&wx[j][d4 * 4];
        acc = fmaf(xa.x, wv.x, acc);
        acc = fmaf(xa.y, wv.y, acc);
        acc = fmaf(xa.z, wv.z, acc);
        acc = fmaf(xa.w, wv.w, acc);
    }
    g_xdbl[(size_t)(t0 + tl) * 36 + j] = acc;
}

// ---------------- dt + selective scan + gate (smem staged) ----------------
__global__ __launch_bounds__(128) void k_scan(const float* __restrict__ dtw,
                                              const float* __restrict__ dtb,
                                              const float* __restrict__ Dp_) {
    int n = blockIdx.x, d = threadIdx.x;
    __shared__ __align__(16) float sxd[1152];
    __shared__ float su[4096], szg[4096];
    size_t nb = (size_t)n * 4096;
    for (int i = d; i < 1152; i += 128) sxd[i] = g_xdbl[(size_t)n * 1152 + i];
    for (int i = d; i < 4096; i += 128) {
        su[i] = g_xa[nb + i];
        szg[i] = g_zg[nb + i];
    }
    __syncthreads();
    float4 wdt = ((const float4*)dtw)[d];
    float bdt = dtb[d], Dp = Dp_[d];
    float A[DST];
    bool fast = true;
#pragma unroll
    for (int s = 0; s < DST; s++) {
        A[s] = g_A[d * DST + s];
        fast = fast && (fabsf(A[s] + (float)(s + 1)) <= 2e-6f * (float)(s + 1));
    }
    float st[DST];
#pragma unroll
    for (int s = 0; s < DST; s++) st[s] = 0.f;
    for (int z = 0; z < ZD; z++) {
        const float* xz = sxd + z * 36;
        float4 h0 = *(const float4*)xz;
        float4 b4[4], c4v[4];
#pragma unroll
        for (int k = 0; k < 4; k++) {
            b4[k]  = *(const float4*)(xz + 4 + 4 * k);
            c4v[k] = *(const float4*)(xz + 20 + 4 * k);
        }
        float Bv[16] = {b4[0].x, b4[0].y, b4[0].z, b4[0].w,
                        b4[1].x, b4[1].y, b4[1].z, b4[1].w,
                        b4[2].x, b4[2].y, b4[2].z, b4[2].w,
                        b4[3].x, b4[3].y, b4[3].z, b4[3].w};
        float Cv[16] = {c4v[0].x, c4v[0].y, c4v[0].z, c4v[0].w,
                        c4v[1].x, c4v[1].y, c4v[1].z, c4v[1].w,
                        c4v[2].x, c4v[2].y, c4v[2].z, c4v[2].w,
                        c4v[3].x, c4v[3].y, c4v[3].z, c4v[3].w};
        float pre = fmaf(wdt.x, h0.x, fmaf(wdt.y, h0.y,
                    fmaf(wdt.z, h0.z, fmaf(wdt.w, h0.w, bdt))));
        float dt = (pre > 15.f) ? pre : log1pf(__expf(pre));
        float u = su[z * 128 + d];
        float du = dt * u;
        float y = 0.f;
        if (fast) {
            float E = __expf(-dt);
            float ep = E;
#pragma unroll
            for (int s = 0; s < DST; s++) {
                st[s] = fmaf(ep, st[s], du * Bv[s]);
                y = fmaf(st[s], Cv[s], y);
                ep *= E;
            }
        } else {
#pragma unroll
            for (int s = 0; s < DST; s++) {
                float e = __expf(dt * A[s]);
                st[s] = fmaf(e, st[s], du * Bv[s]);
                y = fmaf(st[s], Cv[s], y);
            }
        }
        float zg = szg[z * 128 + d];
        g_y[nb + z * 128 + d] = fmaf(Dp, u, y) * fsilu(zg);
    }
}

// ---------------- Wc = proj_w @ out_proj_w ----------------
__global__ __launch_bounds__(256) void k_wc(const float* __restrict__ op,
                                            const float* __restrict__ pj) {
    int idx = blockIdx.x * 256 + threadIdx.x;
    if (idx >= 64 * 128) return;
    int o = idx >> 7, dd = idx & 127;
    float acc = 0.f;
#pragma unroll 8
    for (int c = 0; c < 64; c++)
        acc = fmaf(pj[o * 64 + c], op[c * 128 + dd], acc);
    g_wc[idx] = acc;
}

// ---------------- seqout = y @ Wc^T + proj_b (vectorized) ----------------
__global__ __launch_bounds__(256) void k_outproj(const float* __restrict__ pb) {
    __shared__ __align__(16) float tok[64][68];
    __shared__ __align__(16) float wsm[64][68];
    int tid = threadIdx.x;
    int t0 = blockIdx.x * 64;
    int tidt = tid >> 4, tidj = tid & 15;
    float acc[4][4] = {};
    for (int kc = 0; kc < 2; kc++) {
        __syncthreads();
        for (int idx = tid; idx < 4096; idx += 256) {
            int r = idx >> 6, k = idx & 63;
            tok[r][k] = g_y[(size_t)(t0 + r) * DI + kc * 64 + k];
            wsm[r][k] = g_wc[r * DI + kc * 64 + k];
        }
        __syncthreads();
#pragma unroll
        for (int c4 = 0; c4 < 16; c4++) {
            float4 a[4], wv[4];
#pragma unroll
            for (int i = 0; i < 4; i++) a[i] = *(const float4*)&tok[tidt * 4 + i][c4 * 4];
#pragma unroll
            for (int j = 0; j < 4; j++) wv[j] = *(const float4*)&wsm[tidj * 4 + j][c4 * 4];
#pragma unroll
            for (int i = 0; i < 4; i++)
#pragma unroll
                for (int j = 0; j < 4; j++) {
                    acc[i][j] = fmaf(a[i].x, wv[j].x, acc[i][j]);
                    acc[i][j] = fmaf(a[i].y, wv[j].y, acc[i][j]);
                    acc[i][j] = fmaf(a[i].z, wv[j].z, acc[i][j]);
                    acc[i][j] = fmaf(a[i].w, wv[j].w, acc[i][j]);
                }
        }
    }
#pragma unroll
    for (int i = 0; i < 4; i++) {
        size_t t = t0 + tidt * 4 + i;
        float4 v;
        v.x = acc[i][0] + pb[tidj * 4 + 0];
        v.y = acc[i][1] + pb[tidj * 4 + 1];
        v.z = acc[i][2] + pb[tidj * 4 + 2];
        v.w = acc[i][3] + pb[tidj * 4 + 3];
        *(float4*)(g_seqout + t * 64 + tidj * 4) = v;
    }
}

// ---------------- stats for pn over seqout ----------------
__global__ __launch_bounds__(256) void k_stats3() {
    int tid = threadIdx.x;
    size_t base = (size_t)blockIdx.x * 16384;
    float s = 0.f, q = 0.f;
    for (int i = tid; i < 16384; i += 256) {
        float v = g_seqout[base + i];
        s += v; q += v * v;
    }
    int c = tid & 63, grp = tid >> 6;
    __shared__ float rs[4][64], rq[4][64];
    rs[grp][c] = s; rq[grp][c] = q;
    __syncthreads();
    if (tid < 64) {
        double S = 0.0, Q = 0.0;
#pragma unroll
        for (int g2 = 0; g2 < 4; g2++) { S += rs[g2][tid]; Q += rq[g2][tid]; }
        atomicAdd(&g_dsum[3][tid], S);
        atomicAdd(&g_dsq[3][tid], Q);
    }
}

// ---------------- final: transpose + pn + residual ----------------
__global__ __launch_bounds__(256) void k_final(const float* __restrict__ gg,
                                               const float* __restrict__ bb,
                                               float* __restrict__ out) {
    int z = blockIdx.y, n0 = blockIdx.x * 32, tid = threadIdx.x;
    __shared__ float sm[64][33];
    for (int idx = tid; idx < 2048; idx += 256) {
        int nn = idx >> 6, c = idx & 63;
        sm[c][nn] = g_seqout[((size_t)(n0 + nn) * ZD + z) * 64 + c];
    }
    __syncthreads();
    for (int idx = tid; idx < 2048; idx += 256) {
        int c = idx >> 5, nn = idx & 31;
        float scale = g_istd[3][c] * gg[c];
        float shift = bb[c] - g_mean[3][c] * scale;
        size_t off = ((size_t)c * ZD + z) * HW + n0 + nn;
        out[off] = g_h[off] + fmaf(sm[c][nn], scale, shift);
    }
}

// ---------------- launch ----------------
extern "C" void kernel_launch(void* const* d_in, const int* in_sizes, int n_in,
                              void* d_out, int out_size) {
    const float* x        = (const float*)d_in[0];
    const float* c1_w     = (const float*)d_in[1];
    const float* in1_g    = (const float*)d_in[2];
    const float* in1_b    = (const float*)d_in[3];
    const float* c2_w     = (const float*)d_in[4];
    const float* in2_g    = (const float*)d_in[5];
    const float* in2_b    = (const float*)d_in[6];
    const float* dw_w     = (const float*)d_in[7];
    const float* pw_w     = (const float*)d_in[8];
    const float* inr_g    = (const float*)d_in[9];
    const float* inr_b    = (const float*)d_in[10];
    const float* ln_g     = (const float*)d_in[11];
    const float* ln_b     = (const float*)d_in[12];
    const float* in_proj_w= (const float*)d_in[13];
    const float* conv1d_w = (const float*)d_in[14];
    const float* conv1d_b = (const float*)d_in[15];
    const float* x_proj_w = (const float*)d_in[16];
    const float* dt_proj_w= (const float*)d_in[17];
    const float* dt_proj_b= (const float*)d_in[18];
    const float* A_log    = (const float*)d_in[19];
    const float* D_p      = (const float*)d_in[20];
    const float* out_proj_w=(const float*)d_in[21];
    const float* proj_w   = (const float*)d_in[22];
    const float* proj_b   = (const float*)d_in[23];
    const float* pn_g     = (const float*)d_in[24];
    const float* pn_b     = (const float*)d_in[25];
    float* out = (float*)d_out;

    dim3 b2d(16, 16);

    k_zero<<<1, 256>>>();
    k_prepA<<<8, 256>>>(A_log);
    k_conv1<<<dim3(4, Z1, 8), b2d>>>(x, c1_w);
    k_fin<<<1, 64>>>(0);
    k_hn<<<(CC * Z1 * HW / 4) / 256, 256>>>(in1_g, in1_b);
    k_conv2<<<dim3(4, Z2, 8), b2d>>>(c2_w);
    k_fin<<<1, 64>>>(1);
    k_h<<<8192, 256>>>(in2_g, in2_b);
    k_dw<<<dim3(4, ZD, CC), b2d>>>(dw_w);
    k_pw<<<512, 256>>>(pw_w);
    k_statsR<<<dim3(64, 4), 256>>>();
    k_fin<<<1, 64>>>(2);
    k_x2t<<<dim3(128, ZD), 256>>>(inr_g, inr_b);
    k_inproj<<<NTOK / 64, 256>>>(in_proj_w, ln_g, ln_b);
    k_conv1d<<<4096, 128>>>(conv1d_w, conv1d_b);
    k_xproj<<<NTOK / 16, 576>>>(x_proj_w);
    k_scan<<<4096, 128>>>(dt_proj_w, dt_proj_b, D_p);
    k_wc<<<32, 256>>>(out_proj_w, proj_w);
    k_outproj<<<NTOK / 64, 256>>>(proj_b);
    k_stats3<<<512, 256>>>();
    k_fin<<<1, 64>>>(3);
    k_final<<<dim3(128, ZD), 256>>>(pn_g, pn_b, out);
}

// round 9
// speedup vs baseline: 3.6806x; 1.7290x over previous
#include <cuda_runtime.h>
#include <cuda_bf16.h>
#include <math.h>
#include <stdint.h>

#define ZD 32
#define HW 4096
#define CIN 32
#define CC 64
#define Z1 33
#define Z2 34
#define DI 128
#define NTOK 131072
#define DST 16
#define EPSF 1e-5f

__device__ float g_buf1[CC * Z1 * HW];
__device__ float g_buf2[CC * Z2 * HW];
__device__ uint32_t g_x2 [ZD * HW * CIN];
__device__ uint32_t g_hn2[Z1 * HW * CC];
__device__ uint4 g_wf1h[4608], g_wf1l[4608];
__device__ uint4 g_wf2h[9216], g_wf2l[9216];
__device__ float g_h[CC * ZD * HW];
__device__ float g_dw[CC * ZD * HW];
__device__ float g_pw[CC * ZD * HW];
__device__ float g_x2t[NTOK * CC];
__device__ float g_xin[NTOK * DI];
__device__ float g_zg[NTOK * DI];
__device__ float g_xa[NTOK * DI];
__device__ float g_xdbl[NTOK * 36];
__device__ float g_y[NTOK * DI];
__device__ float g_seqout[NTOK * CC];
__device__ float g_A[DI * DST];
__device__ float g_wc[CC * DI];
__device__ double g_dsum[4][64], g_dsq[4][64];
__device__ float g_mean[4][64], g_istd[4][64];

__device__ __forceinline__ float fsilu(float x) { return x * (1.f / (1.f + __expf(-x))); }
__device__ __forceinline__ float flrelu(float x) { return fmaxf(x, 0.01f * x); }
__device__ __forceinline__ uint32_t pack_split(float v) {
    __nv_bfloat16 hb = __float2bfloat16(v);
    __nv_bfloat16 lb = __float2bfloat16(v - __bfloat162float(hb));
    return (uint32_t)__bfloat16_as_ushort(hb) | ((uint32_t)__bfloat16_as_ushort(lb) << 16);
}
__device__ __forceinline__ uint32_t smem_u32(const void* p) {
    uint32_t a;
    asm("{ .reg .u64 t; cvta.to.shared.u64 t, %1; cvt.u32.u64 %0, t; }" : "=r"(a) : "l"(p));
    return a;
}
__device__ __forceinline__ void ldsm_x2(uint32_t& r0, uint32_t& r1, uint32_t addr) {
    asm volatile("ldmatrix.sync.aligned.m8n8.x2.shared.b16 {%0,%1}, [%2];"
                 : "=r"(r0), "=r"(r1) : "r"(addr));
}
__device__ __forceinline__ void mma_bf16(float* c, const uint4& a, uint32_t b0, uint32_t b1) {
    asm volatile("mma.sync.aligned.m16n8k16.row.col.f32.bf16.bf16.f32 "
                 "{%0,%1,%2,%3}, {%4,%5,%6,%7}, {%8,%9}, {%0,%1,%2,%3};"
                 : "+f"(c[0]), "+f"(c[1]), "+f"(c[2]), "+f"(c[3])
                 : "r"(a.x), "r"(a.y), "r"(a.z), "r"(a.w), "r"(b0), "r"(b1));
}

__device__ __forceinline__ void stat_reduce_256(float s, float q, int tid, double* ds, double* dq) {
#pragma unroll
    for (int o = 16; o > 0; o >>= 1) {
        s += __shfl_down_sync(0xffffffffu, s, o);
        q += __shfl_down_sync(0xffffffffu, q, o);
    }
    __shared__ float shs[8], shq[8];
    if ((tid & 31) == 0) { shs[tid >> 5] = s; shq[tid >> 5] = q; }
    __syncthreads();
    if (tid == 0) {
        float S = 0, Q = 0;
#pragma unroll
        for (int i = 0; i < 8; i++) { S += shs[i]; Q += shq[i]; }
        atomicAdd(ds, (double)S);
        atomicAdd(dq, (double)Q);
    }
}

__global__ void k_zero() {
    int t = threadIdx.x;
    if (t < 256) { ((double*)g_dsum)[t] = 0.0; ((double*)g_dsq)[t] = 0.0; }
}
__global__ void k_prepA(const float* __restrict__ A_log) {
    int i = blockIdx.x * blockDim.x + threadIdx.x;
    if (i < DI * DST) g_A[i] = -expf(A_log[i]);
}
__global__ void k_fin(int w) {
    int c = threadIdx.x;
    if (c >= 64) return;
    const double cnt[4] = {33.0 * 4096, 34.0 * 4096, 131072.0, 131072.0};
    double m = g_dsum[w][c] / cnt[w], v = g_dsq[w][c] / cnt[w] - m * m;
    g_mean[w][c] = (float)m;
    g_istd[w][c] = (float)(1.0 / sqrt(v + 1e-5));
}

// x NCDHW -> HWC packed bf16x2(hi,lo)
__global__ __launch_bounds__(256) void k_prepx(const float* __restrict__ x) {
    int z = blockIdx.x >> 6, y = blockIdx.x & 63, tid = threadIdx.x;
    __shared__ uint32_t sm[64][33];
    for (int i = tid; i < 2048; i += 256) {
        int c = i >> 6, xx = i & 63;
        sm[xx][c] = pack_split(x[((size_t)c * ZD + z) * HW + y * 64 + xx]);
    }
    __syncthreads();
    uint32_t* dst = g_x2 + ((size_t)z * HW + y * 64) * 32;
    for (int i = tid; i < 2048; i += 256) dst[(i >> 5) * 32 + (i & 31)] = sm[i >> 5][i & 31];
}
// buf1 -> lrelu(inorm1) -> HWC packed
__global__ __launch_bounds__(256) void k_hn(const float* __restrict__ gg, const float* __restrict__ bb) {
    int z = blockIdx.x >> 6, y = blockIdx.x & 63, tid = threadIdx.x;
    __shared__ uint32_t sm[64][65];
    for (int i = tid; i < 4096; i += 256) {
        int c = i >> 6, xx = i & 63;
        float sc = g_istd[0][c] * gg[c], sh = bb[c] - g_mean[0][c] * sc;
        sm[xx][c] = pack_split(flrelu(fmaf(g_buf1[((size_t)c * Z1 + z) * HW + y * 64 + xx], sc, sh)));
    }
    __syncthreads();
    uint32_t* dst = g_hn2 + ((size_t)z * HW + y * 64) * 64;
    for (int i = tid; i < 4096; i += 256) dst[i] = sm[i >> 6][i & 63];
}

// weight A-fragments pre-packed per lane: idx = ((tap*NK+ks)*4+cg)*32+lane
template<int WHICH>
__global__ void k_prepwf(const float* __restrict__ w) {
    constexpr int CI = WHICH ? 64 : 32;
    constexpr int NK = CI / 16;
    int idx = blockIdx.x * 256 + threadIdx.x;
    if (idx >= 18 * NK * 4 * 32) return;
    int l = idx & 31, r = idx >> 5;
    int cg = r & 3; r >>= 2;
    int ks = r % NK, tap = r / NK;
    int kz = tap / 9, rr = tap % 9, ky = rr / 3, kx = rr % 3;
    int row = l >> 2, kp = (l & 3) * 2;
    uint32_t hv[4], lv[4];
#pragma unroll
    for (int j = 0; j < 4; j++) {
        int co = cg * 16 + row + (j & 1) * 8;
        int k0 = ks * 16 + kp + (j >> 1) * 8;
        float v0 = w[((co * CI + k0) * 2 + kz) * 9 + ky * 3 + kx];
        float v1 = w[((co * CI + k0 + 1) * 2 + kz) * 9 + ky * 3 + kx];
        __nv_bfloat16 h0 = __float2bfloat16(v0), h1 = __float2bfloat16(v1);
        __nv_bfloat16 l0 = __float2bfloat16(v0 - __bfloat162float(h0));
        __nv_bfloat16 l1 = __float2bfloat16(v1 - __bfloat162float(h1));
        hv[j] = (uint32_t)__bfloat16_as_ushort(h0) | ((uint32_t)__bfloat16_as_ushort(h1) << 16);
        lv[j] = (uint32_t)__bfloat16_as_ushort(l0) | ((uint32_t)__bfloat16_as_ushort(l1) << 16);
    }
    uint4 H = make_uint4(hv[0], hv[1], hv[2], hv[3]);
    uint4 L = make_uint4(lv[0], lv[1], lv[2], lv[3]);
    if (WHICH) { g_wf2h[idx] = H; g_wf2l[idx] = L; }
    else       { g_wf1h[idx] = H; g_wf1l[idx] = L; }
}

// mma.sync conv: block = 128 pos (2 rows) x 64 co, split-bf16 3 terms
template<int WHICH>
__global__ __launch_bounds__(256) void k_convM() {
    constexpr int CI = WHICH ? 64 : 32;
    constexpr int CIP = WHICH ? 72 : 40;
    constexpr int ZIN = WHICH ? Z1 : ZD;
    constexpr int ZOUT = WHICH ? Z2 : Z1;
    constexpr int NK = CI / 16;
    constexpr int HS = 2 * 4 * 66 * CIP * 2;   // bytes per buffer
    const uint32_t* __restrict__ in = WHICH ? g_hn2 : g_x2;
    const uint4* __restrict__ wfh = WHICH ? g_wf2h : g_wf1h;
    const uint4* __restrict__ wfl = WHICH ? g_wf2l : g_wf1l;
    float* __restrict__ outp = WHICH ? g_buf2 : g_buf1;
    extern __shared__ __align__(16) char smc[];
    __nv_bfloat16* bufh = (__nv_bfloat16*)smc;
    __nv_bfloat16* bufl = (__nv_bfloat16*)(smc + HS);
    int tid = threadIdx.x;
    int zo = blockIdx.x >> 5, y0 = (blockIdx.x & 31) * 2;
    constexpr int CHUNKS = CI / 16;
    for (int it = tid; it < 528 * CHUNKS; it += 256) {
        int slot = it / CHUNKS, ch = it - slot * CHUNKS;
        int sz = slot / 264, r = slot - sz * 264;
        int sy = r / 66, sx = r - sy * 66;
        int zz = zo - 1 + sz, yy = y0 - 1 + sy, xx = sx - 1;
        bool ok = (zz >= 0) & (zz < ZIN) & (yy >= 0) & (yy < 64) & (xx >= 0) & (xx < 64);
        uint4 u[4];
        if (ok) {
            const uint4* src = (const uint4*)(in + ((size_t)zz * HW + yy * 64 + xx) * CI + ch * 16);
            u[0] = src[0]; u[1] = src[1]; u[2] = src[2]; u[3] = src[3];
        } else u[0] = u[1] = u[2] = u[3] = make_uint4(0, 0, 0, 0);
        uint32_t* uu = (uint32_t*)u;
        uint4 h0, h1, l0, l1;
        h0.x = __byte_perm(uu[0], uu[1], 0x5410);  h0.y = __byte_perm(uu[2], uu[3], 0x5410);
        h0.z = __byte_perm(uu[4], uu[5], 0x5410);  h0.w = __byte_perm(uu[6], uu[7], 0x5410);
        h1.x = __byte_perm(uu[8], uu[9], 0x5410);  h1.y = __byte_perm(uu[10], uu[11], 0x5410);
        h1.z = __byte_perm(uu[12], uu[13], 0x5410); h1.w = __byte_perm(uu[14], uu[15], 0x5410);
        l0.x = __byte_perm(uu[0], uu[1], 0x7632);  l0.y = __byte_perm(uu[2], uu[3], 0x7632);
        l0.z = __byte_perm(uu[4], uu[5], 0x7632);  l0.w = __byte_perm(uu[6], uu[7], 0x7632);
        l1.x = __byte_perm(uu[8], uu[9], 0x7632);  l1.y = __byte_perm(uu[10], uu[11], 0x7632);
        l1.z = __byte_perm(uu[12], uu[13], 0x7632); l1.w = __byte_perm(uu[14], uu[15], 0x7632);
        int base = slot * CIP + ch * 16;
        *(uint4*)(bufh + base) = h0; *(uint4*)(bufh + base + 8) = h1;
        *(uint4*)(bufl + base) = l0; *(uint4*)(bufl + base + 8) = l1;
    }
    __syncthreads();
    int w = tid >> 5, l = tid & 31;
    int cg = w >> 1, py = w & 1;
    float acc[8][4] = {};
    uint32_t sbh = smem_u32(bufh);
    for (int tap = 0; tap < 18; tap++) {
        int kz = tap / 9, rr = tap % 9, ky = rr / 3, kx = rr % 3;
        int slot0 = (kz * 4 + py + ky) * 66 + kx;
        uint32_t baddr0 = sbh + (uint32_t)((slot0 + (l & 7)) * CIP) * 2 + ((l >> 3) & 1) * 16;
        int widx = (tap * NK) * 128 + cg * 32 + l;
#pragma unroll
        for (int ks = 0; ks < NK; ks++) {
            uint4 ah = __ldg(wfh + widx + ks * 128);
            uint4 al = __ldg(wfl + widx + ks * 128);
            uint32_t ba = baddr0 + ks * 32;
#pragma unroll
            for (int t = 0; t < 8; t++) {
                uint32_t b0h, b1h, b0l, b1l;
                ldsm_x2(b0h, b1h, ba);
                ldsm_x2(b0l, b1l, ba + HS);
                mma_bf16(acc[t], ah, b0h, b1h);
                mma_bf16(acc[t], al, b0h, b1h);
                mma_bf16(acc[t], ah, b0l, b1l);
                ba += 8 * CIP * 2;
            }
        }
    }
    __syncthreads();
    float* cs = (float*)smc;    // [64][128]
    {
        int co = cg * 16 + (l >> 2);
        int p0 = py * 64 + (l & 3) * 2;
#pragma unroll
        for (int t = 0; t < 8; t++) {
            int p = p0 + t * 8;
            cs[co * 128 + p] = acc[t][0];  cs[co * 128 + p + 1] = acc[t][1];
            cs[(co + 8) * 128 + p] = acc[t][2]; cs[(co + 8) * 128 + p + 1] = acc[t][3];
        }
    }
    __syncthreads();
    {
        float4* dstb = (float4*)(outp + (size_t)zo * HW + y0 * 64);
        size_t cstride = (size_t)ZOUT * HW / 4;
        for (int i = tid; i < 2048; i += 256) {
            int c = i >> 5, j = i & 31;
            dstb[c * cstride + j] = ((float4*)(cs + c * 128))[j];
        }
    }
    {
        int c = tid >> 2, q = tid & 3;
        float s = 0, q2 = 0;
#pragma unroll
        for (int j = 0; j < 32; j++) { float v = cs[c * 128 + q * 32 + j]; s += v; q2 += v * v; }
#pragma unroll
        for (int o = 2; o > 0; o >>= 1) {
            s += __shfl_down_sync(0xffffffffu, s, o);
            q2 += __shfl_down_sync(0xffffffffu, q2, o);
        }
        __shared__ float ps[64], pq[64];
        if (q == 0) { ps[c] = s; pq[c] = q2; }
        __syncthreads();
        if (tid < 64) {
            atomicAdd(&g_dsum[WHICH][tid], (double)ps[tid]);
            atomicAdd(&g_dsq[WHICH][tid], (double)pq[tid]);
        }
    }
}

__global__ __launch_bounds__(256) void k_h(const float* __restrict__ gg, const float* __restrict__ bb) {
    int base = (blockIdx.x * 256 + threadIdx.x) * 4;
    int c = base >> 17, off = base & 131071;
    float sc = g_istd[1][c] * gg[c], sh = bb[c] - g_mean[1][c] * sc;
    float4 r = *(const float4*)(g_buf2 + (size_t)c * (Z2 * HW) + off);
    float4 o;
    o.x = flrelu(fmaf(r.x, sc, sh)); o.y = flrelu(fmaf(r.y, sc, sh));
    o.z = flrelu(fmaf(r.z, sc, sh)); o.w = flrelu(fmaf(r.w, sc, sh));
    *(float4*)(g_h + base) = o;
}

__global__ __launch_bounds__(256) void k_dw(const float* __restrict__ w) {
    const int tileR = blockIdx.x * 16, z = blockIdx.y, c = blockIdx.z;
    __shared__ __align__(16) float ins[18 * 68];
    const int tx = threadIdx.x, ty = threadIdx.y, tid = ty * 16 + tx;
    float wv[9];
#pragma unroll
    for (int i = 0; i < 9; i++) wv[i] = __ldg(w + c * 9 + i);
    const float* xp = g_h + ((size_t)c * ZD + z) * HW;
    for (int i = tid; i < 18 * 68; i += 256) {
        int r = i / 68, c2 = i - r * 68, gr = tileR + r - 1, gc = c2 - 1;
        ins[i] = (gr >= 0 && gr < 64 && gc >= 0 && gc < 64) ? xp[gr * 64 + gc] : 0.f;
    }
    __syncthreads();
    float a0 = 0, a1 = 0, a2 = 0, a3 = 0;
#pragma unroll
    for (int ky = 0; ky < 3; ky++) {
        const float4* rp = (const float4*)(ins + (ty + ky) * 68 + (tx << 2));
        float4 va = rp[0], vb = rp[1];
        float w0 = wv[3 * ky], w1 = wv[3 * ky + 1], w2 = wv[3 * ky + 2];
        a0 = fmaf(w0, va.x, fmaf(w1, va.y, fmaf(w2, va.z, a0)));
        a1 = fmaf(w0, va.y, fmaf(w1, va.z, fmaf(w2, va.w, a1)));
        a2 = fmaf(w0, va.z, fmaf(w1, va.w, fmaf(w2, vb.x, a2)));
        a3 = fmaf(w0, va.w, fmaf(w1, vb.x, fmaf(w2, vb.y, a3)));
    }
    *(float4*)(g_dw + ((size_t)c * ZD + z) * HW + (tileR + ty) * 64 + (tx << 2)) = make_float4(a0, a1, a2, a3);
}

__global__ __launch_bounds__(256) void k_pw(const float* __restrict__ w) {
    __shared__ __align__(16) float wsm[64 * 64];
    int tid = threadIdx.x;
    for (int i = tid; i < 4096; i += 256) wsm[i] = w[(i & 63) * 64 + (i >> 6)];
    __syncthreads();
    int p = blockIdx.x * 256 + tid;
    float acc[64];
#pragma unroll
    for (int co = 0; co < 64; co++) acc[co] = 0.f;
    for (int ci = 0; ci < 64; ci++) {
        float v = g_dw[(size_t)ci * (ZD * HW) + p];
        const float4* wr = (const float4*)(wsm + ci * 64);
#pragma unroll
        for (int c4 = 0; c4 < 16; c4++) {
            float4 wv = wr[c4];
            acc[c4 * 4] = fmaf(wv.x, v, acc[c4 * 4]);
            acc[c4 * 4 + 1] = fmaf(wv.y, v, acc[c4 * 4 + 1]);
            acc[c4 * 4 + 2] = fmaf(wv.z, v, acc[c4 * 4 + 2]);
            acc[c4 * 4 + 3] = fmaf(wv.w, v, acc[c4 * 4 + 3]);
        }
    }
#pragma unroll
    for (int co = 0; co < 64; co++) g_pw[(size_t)co * (ZD * HW) + p] = acc[co];
}

__global__ __launch_bounds__(256) void k_statsR() {
    int c = blockIdx.x, tid = threadIdx.x;
    size_t base = (size_t)c * (ZD * HW) + (size_t)blockIdx.y * 32768;
    float s = 0, q = 0;
    for (int i = tid; i < 32768; i += 256) { float v = g_pw[base + i]; s += v; q += v * v; }
    stat_reduce_256(s, q, tid, &g_dsum[2][c], &g_dsq[2][c]);
}

__global__ __launch_bounds__(256) void k_x2t(const float* __restrict__ gg, const float* __restrict__ bb) {
    int z = blockIdx.y, n0 = blockIdx.x * 32, tid = threadIdx.x;
    __shared__ float sm[64][33];
    for (int i = tid; i < 2048; i += 256) {
        int c = i >> 5, nn = i & 31;
        size_t off = (size_t)c * (ZD * HW) + (size_t)z * HW + n0 + nn;
        float sc = g_istd[2][c] * gg[c], sh = bb[c] - g_mean[2][c] * sc;
        sm[c][nn] = g_h[off] + fsilu(fmaf(g_pw[off], sc, sh));
    }
    __syncthreads();
    for (int i = tid; i < 2048; i += 256) {
        int nn = i >> 6, c = i & 63;
        g_x2t[((size_t)(n0 + nn) * ZD + z) * 64 + c] = sm[c][nn];
    }
}

__global__ __launch_bounds__(256) void k_inproj(const float* __restrict__ W,
                                                const float* __restrict__ lg, const float* __restrict__ lb) {
    __shared__ __align__(16) float tok[64][68];
    __shared__ __align__(16) float wsm[64][68];
    int tid = threadIdx.x, t0 = blockIdx.x * 64;
    int wi = tid >> 5, lane = tid & 31;
    float g0 = lg[lane], g1 = lg[lane + 32], b0 = lb[lane], b1 = lb[lane + 32];
    for (int tt = wi; tt < 64; tt += 8) {
        int t = t0 + tt;
        float v0 = g_x2t[(size_t)t * 64 + lane], v1 = g_x2t[(size_t)t * 64 + lane + 32];
        float s = v0 + v1, q = v0 * v0 + v1 * v1;
#pragma unroll
        for (int o = 16; o > 0; o >>= 1) {
            s += __shfl_xor_sync(0xffffffffu, s, o);
            q += __shfl_xor_sync(0xffffffffu, q, o);
        }
        float mean = s * (1.f / 64.f), var = q * (1.f / 64.f) - mean * mean;
        float istd = rsqrtf(var + EPSF);
        tok[tt][lane] = (v0 - mean) * istd * g0 + b0;
        tok[tt][lane + 32] = (v1 - mean) * istd * g1 + b1;
    }
    int tidt = tid >> 4, tidj = tid & 15;
    for (int jc = 0; jc < 4; jc++) {
        __syncthreads();
        for (int i = tid; i < 4096; i += 256) wsm[i >> 6][i & 63] = W[(jc * 64 + (i >> 6)) * 64 + (i & 63)];
        __syncthreads();
        float acc[4][4] = {};
#pragma unroll
        for (int c4 = 0; c4 < 16; c4++) {
            float4 a[4], wv[4];
#pragma unroll
            for (int i = 0; i < 4; i++) a[i] = *(const float4*)&tok[tidt * 4 + i][c4 * 4];
#pragma unroll
            for (int j = 0; j < 4; j++) wv[j] = *(const float4*)&wsm[tidj * 4 + j][c4 * 4];
#pragma unroll
            for (int i = 0; i < 4; i++)
#pragma unroll
                for (int j = 0; j < 4; j++) {
                    acc[i][j] = fmaf(a[i].x, wv[j].x, acc[i][j]);
                    acc[i][j] = fmaf(a[i].y, wv[j].y, acc[i][j]);
                    acc[i][j] = fmaf(a[i].z, wv[j].z, acc[i][j]);
                    acc[i][j] = fmaf(a[i].w, wv[j].w, acc[i][j]);
                }
        }
#pragma unroll
        for (int i = 0; i < 4; i++) {
            size_t t = t0 + tidt * 4 + i;
            float4 v = make_float4(acc[i][0], acc[i][1], acc[i][2], acc[i][3]);
            if (jc < 2) *(float4*)(g_xin + t * 128 + jc * 64 + tidj * 4) = v;
            else        *(float4*)(g_zg + t * 128 + (jc - 2) * 64 + tidj * 4) = v;
        }
    }
}

__global__ __launch_bounds__(128) void k_conv1d(const float* __restrict__ w, const float* __restrict__ b) {
    int n = blockIdx.x, d = threadIdx.x;
    __shared__ float sx[4096];
    size_t nb = (size_t)n * 4096;
    for (int i = d; i < 4096; i += 128) sx[i] = g_xin[nb + i];
    __syncthreads();
    float4 wv = ((const float4*)w)[d];
    float bias = b[d], x0 = 0, x1 = 0, x2v = 0;
#pragma unroll 4
    for (int z = 0; z < ZD; z++) {
        float xn = sx[z * 128 + d];
        float v = fmaf(wv.x, x0, fmaf(wv.y, x1, fmaf(wv.z, x2v, fmaf(wv.w, xn, bias))));
        g_xa[nb + z * 128 + d] = fsilu(v);
        x0 = x1; x1 = x2v; x2v = xn;
    }
}

__global__ __launch_bounds__(576) void k_xproj(const float* __restrict__ W) {
    __shared__ __align__(16) float xs[16][132];
    __shared__ __align__(16) float wx[36][132];
    int tid = threadIdx.x, t0 = blockIdx.x * 16;
    for (int i = tid; i < 2048; i += 576) xs[i >> 7][i & 127] = g_xa[(size_t)(t0 + (i >> 7)) * DI + (i & 127)];
    for (int i = tid; i < 4608; i += 576) wx[i >> 7][i & 127] = W[i];
    __syncthreads();
    int j = tid % 36, tl = tid / 36;
    float acc = 0;
#pragma unroll
    for (int d4 = 0; d4 < 32; d4++) {
        float4 xa = *(const float4*)&xs[tl][d4 * 4];
        float4 wv = *(const float4*)&wx[j][d4 * 4];
        acc = fmaf(xa.x, wv.x, fmaf(xa.y, wv.y, fmaf(xa.z, wv.z, fmaf(xa.w, wv.w, acc))));
    }
    g_xdbl[(size_t)(t0 + tl) * 36 + j] = acc;
}

__global__ __launch_bounds__(128) void k_scan(const float* __restrict__ dtw,
                                              const float* __restrict__ dtb, const float* __restrict__ Dp_) {
    int n = blockIdx.x, d = threadIdx.x;
    __shared__ __align__(16) float sxd[1152];
    __shared__ float su[4096], szg[4096];
    size_t nb = (size_t)n * 4096;
    for (int i = d; i < 1152; i += 128) sxd[i] = g_xdbl[(size_t)n * 1152 + i];
    for (int i = d; i < 4096; i += 128) { su[i] = g_xa[nb + i]; szg[i] = g_zg[nb + i]; }
    __syncthreads();
    float4 wdt = ((const float4*)dtw)[d];
    float bdt = dtb[d], Dp = Dp_[d];
    float A[DST];
    bool fast = true;
#pragma unroll
    for (int s = 0; s < DST; s++) {
        A[s] = g_A[d * DST + s];
        fast = fast && (fabsf(A[s] + (float)(s + 1)) <= 2e-6f * (float)(s + 1));
    }
    float st[DST];
#pragma unroll
    for (int s = 0; s < DST; s++) st[s] = 0.f;
    for (int z = 0; z < ZD; z++) {
        const float* xz = sxd + z * 36;
        float4 h0 = *(const float4*)xz;
        float Bv[16], Cv[16];
#pragma unroll
        for (int k = 0; k < 4; k++) {
            float4 bb4 = *(const float4*)(xz + 4 + 4 * k);
            float4 cc4 = *(const float4*)(xz + 20 + 4 * k);
            Bv[4 * k] = bb4.x; Bv[4 * k + 1] = bb4.y; Bv[4 * k + 2] = bb4.z; Bv[4 * k + 3] = bb4.w;
            Cv[4 * k] = cc4.x; Cv[4 * k + 1] = cc4.y; Cv[4 * k + 2] = cc4.z; Cv[4 * k + 3] = cc4.w;
        }
        float pre = fmaf(wdt.x, h0.x, fmaf(wdt.y, h0.y, fmaf(wdt.z, h0.z, fmaf(wdt.w, h0.w, bdt))));
        float dt = (pre > 15.f) ? pre : log1pf(__expf(pre));
        float u = su[z * 128 + d], du = dt * u, yv = 0;
        if (fast) {
            float E = __expf(-dt), ep = E;
#pragma unroll
            for (int s = 0; s < DST; s++) {
                st[s] = fmaf(ep, st[s], du * Bv[s]);
                yv = fmaf(st[s], Cv[s], yv);
                ep *= E;
            }
        } else {
#pragma unroll
            for (int s = 0; s < DST; s++) {
                float e = __expf(dt * A[s]);
                st[s] = fmaf(e, st[s], du * Bv[s]);
                yv = fmaf(st[s], Cv[s], yv);
            }
        }
        g_y[nb + z * 128 + d] = fmaf(Dp, u, yv) * fsilu(szg[z * 128 + d]);
    }
}

__global__ __launch_bounds__(256) void k_wc(const float* __restrict__ op, const float* __restrict__ pj) {
    int idx = blockIdx.x * 256 + threadIdx.x;
    if (idx >= 64 * 128) return;
    int o = idx >> 7, dd = idx & 127;
    float acc = 0;
#pragma unroll 8
    for (int c = 0; c < 64; c++) acc = fmaf(pj[o * 64 + c], op[c * 128 + dd], acc);
    g_wc[idx] = acc;
}

__global__ __launch_bounds__(256) void k_outproj(const float* __restrict__ pb) {
    __shared__ __align__(16) float tok[64][68];
    __shared__ __align__(16) float wsm[64][68];
    int tid = threadIdx.x, t0 = blockIdx.x * 64;
    int tidt = tid >> 4, tidj = tid & 15;
    float acc[4][4] = {};
    for (int kc = 0; kc < 2; kc++) {
        __syncthreads();
        for (int i = tid; i < 4096; i += 256) {
            int r = i >> 6, k = i & 63;
            tok[r][k] = g_y[(size_t)(t0 + r) * DI + kc * 64 + k];
            wsm[r][k] = g_wc[r * DI + kc * 64 + k];
        }
        __syncthreads();
#pragma unroll
        for (int c4 = 0; c4 < 16; c4++) {
            float4 a[4], wv[4];
#pragma unroll
            for (int i = 0; i < 4; i++) a[i] = *(const float4*)&tok[tidt * 4 + i][c4 * 4];
#pragma unroll
            for (int j = 0; j < 4; j++) wv[j] = *(const float4*)&wsm[tidj * 4 + j][c4 * 4];
#pragma unroll
            for (int i = 0; i < 4; i++)
#pragma unroll
                for (int j = 0; j < 4; j++) {
                    acc[i][j] = fmaf(a[i].x, wv[j].x, acc[i][j]);
                    acc[i][j] = fmaf(a[i].y, wv[j].y, acc[i][j]);
                    acc[i][j] = fmaf(a[i].z, wv[j].z, acc[i][j]);
                    acc[i][j] = fmaf(a[i].w, wv[j].w, acc[i][j]);
                }
        }
    }
#pragma unroll
    for (int i = 0; i < 4; i++) {
        size_t t = t0 + tidt * 4 + i;
        float4 v;
        v.x = acc[i][0] + pb[tidj * 4]; v.y = acc[i][1] + pb[tidj * 4 + 1];
        v.z = acc[i][2] + pb[tidj * 4 + 2]; v.w = acc[i][3] + pb[tidj * 4 + 3];
        *(float4*)(g_seqout + t * 64 + tidj * 4) = v;
    }
}

__global__ __launch_bounds__(256) void k_stats3() {
    int tid = threadIdx.x;
    size_t base = (size_t)blockIdx.x * 16384;
    float s = 0, q = 0;
    for (int i = tid; i < 16384; i += 256) { float v = g_seqout[base + i]; s += v; q += v * v; }
    int c = tid & 63, grp = tid >> 6;
    __shared__ float rs[4][64], rq[4][64];
    rs[grp][c] = s; rq[grp][c] = q;
    __syncthreads();
    if (tid < 64) {
        double S = 0, Q = 0;
#pragma unroll
        for (int g2 = 0; g2 < 4; g2++) { S += rs[g2][tid]; Q += rq[g2][tid]; }
        atomicAdd(&g_dsum[3][tid], S);
        atomicAdd(&g_dsq[3][tid], Q);
    }
}

__global__ __launch_bounds__(256) void k_final(const float* __restrict__ gg,
                                               const float* __restrict__ bb, float* __restrict__ out) {
    int z = blockIdx.y, n0 = blockIdx.x * 32, tid = threadIdx.x;
    __shared__ float sm[64][33];
    for (int i = tid; i < 2048; i += 256) {
        int nn = i >> 6, c = i & 63;
        sm[c][nn] = g_seqout[((size_t)(n0 + nn) * ZD + z) * 64 + c];
    }
    __syncthreads();
    for (int i = tid; i < 2048; i += 256) {
        int c = i >> 5, nn = i & 31;
        float sc = g_istd[3][c] * gg[c], sh = bb[c] - g_mean[3][c] * sc;
        size_t off = ((size_t)c * ZD + z) * HW + n0 + nn;
        out[off] = g_h[off] + fmaf(sm[c][nn], sc, sh);
    }
}

extern "C" void kernel_launch(void* const* d_in, const int* in_sizes, int n_in,
                              void* d_out, int out_size) {
    const float* x = (const float*)d_in[0];
    const float* c1_w = (const float*)d_in[1];
    const float* in1_g = (const float*)d_in[2];
    const float* in1_b = (const float*)d_in[3];
    const float* c2_w = (const float*)d_in[4];
    const float* in2_g = (const float*)d_in[5];
    const float* in2_b = (const float*)d_in[6];
    const float* dw_w = (const float*)d_in[7];
    const float* pw_w = (const float*)d_in[8];
    const float* inr_g = (const float*)d_in[9];
    const float* inr_b = (const float*)d_in[10];
    const float* ln_g = (const float*)d_in[11];
    const float* ln_b = (const float*)d_in[12];
    const float* in_proj_w = (const float*)d_in[13];
    const float* conv1d_w = (const float*)d_in[14];
    const float* conv1d_b = (const float*)d_in[15];
    const float* x_proj_w = (const float*)d_in[16];
    const float* dt_proj_w = (const float*)d_in[17];
    const float* dt_proj_b = (const float*)d_in[18];
    const float* A_log = (const float*)d_in[19];
    const float* D_p = (const float*)d_in[20];
    const float* out_proj_w = (const float*)d_in[21];
    const float* proj_w = (const float*)d_in[22];
    const float* proj_b = (const float*)d_in[23];
    const float* pn_g = (const float*)d_in[24];
    const float* pn_b = (const float*)d_in[25];
    float* out = (float*)d_out;

    const int SMEM1 = 2 * (2 * 4 * 66 * 40 * 2);   // 84480
    const int SMEM2 = 2 * (2 * 4 * 66 * 72 * 2);   // 152064
    cudaFuncSetAttribute(k_convM<0>, cudaFuncAttributeMaxDynamicSharedMemorySize, SMEM1);
    cudaFuncSetAttribute(k_convM<1>, cudaFuncAttributeMaxDynamicSharedMemorySize, SMEM2);

    dim3 b2d(16, 16);
    k_zero<<<1, 256>>>();
    k_prepA<<<8, 256>>>(A_log);
    k_prepx<<<ZD * 64, 256>>>(x);
    k_prepwf<0><<<18, 256>>>(c1_w);
    k_prepwf<1><<<36, 256>>>(c2_w);
    k_convM<0><<<Z1 * 32, 256, SMEM1>>>();
    k_fin<<<1, 64>>>(0);
    k_hn<<<Z1 * 64, 256>>>(in1_g, in1_b);
    k_convM<1><<<Z2 * 32, 256, SMEM2>>>();
    k_fin<<<1, 64>>>(1);
    k_h<<<8192, 256>>>(in2_g, in2_b);
    k_dw<<<dim3(4, ZD, CC), b2d>>>(dw_w);
    k_pw<<<512, 256>>>(pw_w);
    k_statsR<<<dim3(64, 4), 256>>>();
    k_fin<<<1, 64>>>(2);
    k_x2t<<<dim3(128, ZD), 256>>>(inr_g, inr_b);
    k_inproj<<<NTOK / 64, 256>>>(in_proj_w, ln_g, ln_b);
    k_conv1d<<<4096, 128>>>(conv1d_w, conv1d_b);
    k_xproj<<<NTOK / 16, 576>>>(x_proj_w);
    k_scan<<<4096, 128>>>(dt_proj_w, dt_proj_b, D_p);
    k_wc<<<32, 256>>>(out_proj_w, proj_w);
    k_outproj<<<NTOK / 64, 256>>>(proj_b);
    k_stats3<<<512, 256>>>();
    k_fin<<<1, 64>>>(3);
    k_final<<<dim3(128, ZD), 256>>>(pn_g, pn_b, out);
}

// round 10
// speedup vs baseline: 4.8881x; 1.3281x over previous
#include <cuda_runtime.h>
#include <cuda_bf16.h>
#include <math.h>
#include <stdint.h>

#define ZD 32
#define HW 4096
#define CIN 32
#define CC 64
#define Z1 33
#define Z2 34
#define DI 128
#define NTOK 131072
#define DST 16
#define EPSF 1e-5f

__device__ float g_buf1[CC * Z1 * HW];
__device__ float g_buf2[CC * Z2 * HW];
__device__ uint32_t g_x2 [ZD * HW * CIN];
__device__ uint32_t g_hn2[Z1 * HW * CC];
__device__ uint4 g_wf1h[4608], g_wf1l[4608];
__device__ uint4 g_wf2h[9216], g_wf2l[9216];
__device__ uint4 g_wih[2048], g_wil[2048];
__device__ uint4 g_woh[1024], g_wol[1024];
__device__ float g_h[CC * ZD * HW];
__device__ float g_dw[CC * ZD * HW];
__device__ float g_pw[CC * ZD * HW];
__device__ float g_x2t[NTOK * CC];
__device__ float g_xin[NTOK * DI];
__device__ float g_zg[NTOK * DI];
__device__ float g_xa[NTOK * DI];
__device__ float g_xdbl[NTOK * 36];
__device__ float g_y[NTOK * DI];
__device__ float g_seqout[NTOK * CC];
__device__ float g_A[DI * DST];
__device__ float g_wc[CC * DI];
__device__ double g_dsum[4][64], g_dsq[4][64];
__device__ float g_mean[4][64], g_istd[4][64];

__device__ __forceinline__ float fsilu(float x) { return x * (1.f / (1.f + __expf(-x))); }
__device__ __forceinline__ float flrelu(float x) { return fmaxf(x, 0.01f * x); }
__device__ __forceinline__ uint32_t pack_split(float v) {
    __nv_bfloat16 hb = __float2bfloat16(v);
    __nv_bfloat16 lb = __float2bfloat16(v - __bfloat162float(hb));
    return (uint32_t)__bfloat16_as_ushort(hb) | ((uint32_t)__bfloat16_as_ushort(lb) << 16);
}
__device__ __forceinline__ uint32_t smem_u32(const void* p) {
    uint32_t a;
    asm("{ .reg .u64 t; cvta.to.shared.u64 t, %1; cvt.u32.u64 %0, t; }" : "=r"(a) : "l"(p));
    return a;
}
__device__ __forceinline__ void ldsm_x2(uint32_t& r0, uint32_t& r1, uint32_t addr) {
    asm volatile("ldmatrix.sync.aligned.m8n8.x2.shared.b16 {%0,%1}, [%2];"
                 : "=r"(r0), "=r"(r1) : "r"(addr));
}
__device__ __forceinline__ void mma_bf16(float* c, const uint4& a, uint32_t b0, uint32_t b1) {
    asm volatile("mma.sync.aligned.m16n8k16.row.col.f32.bf16.bf16.f32 "
                 "{%0,%1,%2,%3}, {%4,%5,%6,%7}, {%8,%9}, {%0,%1,%2,%3};"
                 : "+f"(c[0]), "+f"(c[1]), "+f"(c[2]), "+f"(c[3])
                 : "r"(a.x), "r"(a.y), "r"(a.z), "r"(a.w), "r"(b0), "r"(b1));
}
__device__ __forceinline__ void split2(float v0, float v1, uint32_t& hv, uint32_t& lv) {
    __nv_bfloat16 h0 = __float2bfloat16(v0), h1 = __float2bfloat16(v1);
    __nv_bfloat16 l0 = __float2bfloat16(v0 - __bfloat162float(h0));
    __nv_bfloat16 l1 = __float2bfloat16(v1 - __bfloat162float(h1));
    hv = (uint32_t)__bfloat16_as_ushort(h0) | ((uint32_t)__bfloat16_as_ushort(h1) << 16);
    lv = (uint32_t)__bfloat16_as_ushort(l0) | ((uint32_t)__bfloat16_as_ushort(l1) << 16);
}

__device__ __forceinline__ void stat_reduce_256(float s, float q, int tid, double* ds, double* dq) {
#pragma unroll
    for (int o = 16; o > 0; o >>= 1) {
        s += __shfl_down_sync(0xffffffffu, s, o);
        q += __shfl_down_sync(0xffffffffu, q, o);
    }
    __shared__ float shs[8], shq[8];
    if ((tid & 31) == 0) { shs[tid >> 5] = s; shq[tid >> 5] = q; }
    __syncthreads();
    if (tid == 0) {
        float S = 0, Q = 0;
#pragma unroll
        for (int i = 0; i < 8; i++) { S += shs[i]; Q += shq[i]; }
        atomicAdd(ds, (double)S);
        atomicAdd(dq, (double)Q);
    }
}

__global__ void k_zero() {
    int t = threadIdx.x;
    if (t < 256) { ((double*)g_dsum)[t] = 0.0; ((double*)g_dsq)[t] = 0.0; }
}
__global__ void k_prepA(const float* __restrict__ A_log) {
    int i = blockIdx.x * blockDim.x + threadIdx.x;
    if (i < DI * DST) g_A[i] = -expf(A_log[i]);
}
__global__ void k_fin(int w) {
    int c = threadIdx.x;
    if (c >= 64) return;
    const double cnt[4] = {33.0 * 4096, 34.0 * 4096, 131072.0, 131072.0};
    double m = g_dsum[w][c] / cnt[w], v = g_dsq[w][c] / cnt[w] - m * m;
    g_mean[w][c] = (float)m;
    g_istd[w][c] = (float)(1.0 / sqrt(v + 1e-5));
}

__global__ __launch_bounds__(256) void k_prepx(const float* __restrict__ x) {
    int z = blockIdx.x >> 6, y = blockIdx.x & 63, tid = threadIdx.x;
    __shared__ uint32_t sm[64][33];
    for (int i = tid; i < 2048; i += 256) {
        int c = i >> 6, xx = i & 63;
        sm[xx][c] = pack_split(x[((size_t)c * ZD + z) * HW + y * 64 + xx]);
    }
    __syncthreads();
    uint32_t* dst = g_x2 + ((size_t)z * HW + y * 64) * 32;
    for (int i = tid; i < 2048; i += 256) dst[(i >> 5) * 32 + (i & 31)] = sm[i >> 5][i & 31];
}
__global__ __launch_bounds__(256) void k_hn(const float* __restrict__ gg, const float* __restrict__ bb) {
    int z = blockIdx.x >> 6, y = blockIdx.x & 63, tid = threadIdx.x;
    __shared__ uint32_t sm[64][65];
    for (int i = tid; i < 4096; i += 256) {
        int c = i >> 6, xx = i & 63;
        float sc = g_istd[0][c] * gg[c], sh = bb[c] - g_mean[0][c] * sc;
        sm[xx][c] = pack_split(flrelu(fmaf(g_buf1[((size_t)c * Z1 + z) * HW + y * 64 + xx], sc, sh)));
    }
    __syncthreads();
    uint32_t* dst = g_hn2 + ((size_t)z * HW + y * 64) * 64;
    for (int i = tid; i < 4096; i += 256) dst[i] = sm[i >> 6][i & 63];
}

template<int WHICH>
__global__ void k_prepwf(const float* __restrict__ w) {
    constexpr int CI = WHICH ? 64 : 32;
    constexpr int NK = CI / 16;
    int idx = blockIdx.x * 256 + threadIdx.x;
    if (idx >= 18 * NK * 4 * 32) return;
    int l = idx & 31, r = idx >> 5;
    int cg = r & 3; r >>= 2;
    int ks = r % NK, tap = r / NK;
    int kz = tap / 9, rr = tap % 9, ky = rr / 3, kx = rr % 3;
    int row = l >> 2, kp = (l & 3) * 2;
    uint32_t hv[4], lv[4];
#pragma unroll
    for (int j = 0; j < 4; j++) {
        int co = cg * 16 + row + (j & 1) * 8;
        int k0 = ks * 16 + kp + (j >> 1) * 8;
        split2(w[((co * CI + k0) * 2 + kz) * 9 + ky * 3 + kx],
               w[((co * CI + k0 + 1) * 2 + kz) * 9 + ky * 3 + kx], hv[j], lv[j]);
    }
    uint4 H = make_uint4(hv[0], hv[1], hv[2], hv[3]);
    uint4 L = make_uint4(lv[0], lv[1], lv[2], lv[3]);
    if (WHICH) { g_wf2h[idx] = H; g_wf2l[idx] = L; }
    else       { g_wf1h[idx] = H; g_wf1l[idx] = L; }
}
// in_proj_w 256x64 fragments: idx = (ks*16+cg)*32+l
__global__ void k_prepwi(const float* __restrict__ w) {
    int idx = blockIdx.x * 256 + threadIdx.x;
    if (idx >= 2048) return;
    int l = idx & 31, r = idx >> 5;
    int cg = r & 15, ks = r >> 4;
    int row = l >> 2, kp = (l & 3) * 2;
    uint32_t hv[4], lv[4];
#pragma unroll
    for (int j = 0; j < 4; j++) {
        int co = cg * 16 + row + (j & 1) * 8;
        int k0 = ks * 16 + kp + (j >> 1) * 8;
        split2(w[co * 64 + k0], w[co * 64 + k0 + 1], hv[j], lv[j]);
    }
    g_wih[idx] = make_uint4(hv[0], hv[1], hv[2], hv[3]);
    g_wil[idx] = make_uint4(lv[0], lv[1], lv[2], lv[3]);
}
// Wc 64x128 fragments: idx = (ks*4+cg)*32+l
__global__ void k_prepwo() {
    int idx = blockIdx.x * 256 + threadIdx.x;
    if (idx >= 1024) return;
    int l = idx & 31, r = idx >> 5;
    int cg = r & 3, ks = r >> 2;
    int row = l >> 2, kp = (l & 3) * 2;
    uint32_t hv[4], lv[4];
#pragma unroll
    for (int j = 0; j < 4; j++) {
        int co = cg * 16 + row + (j & 1) * 8;
        int k0 = ks * 16 + kp + (j >> 1) * 8;
        split2(g_wc[co * 128 + k0], g_wc[co * 128 + k0 + 1], hv[j], lv[j]);
    }
    g_woh[idx] = make_uint4(hv[0], hv[1], hv[2], hv[3]);
    g_wol[idx] = make_uint4(lv[0], lv[1], lv[2], lv[3]);
}

template<int WHICH>
__global__ __launch_bounds__(256) void k_convM() {
    constexpr int CI = WHICH ? 64 : 32;
    constexpr int CIP = WHICH ? 72 : 40;
    constexpr int ZIN = WHICH ? Z1 : ZD;
    constexpr int ZOUT = WHICH ? Z2 : Z1;
    constexpr int NK = CI / 16;
    constexpr int HS = 2 * 4 * 66 * CIP * 2;
    const uint32_t* __restrict__ in = WHICH ? g_hn2 : g_x2;
    const uint4* __restrict__ wfh = WHICH ? g_wf2h : g_wf1h;
    const uint4* __restrict__ wfl = WHICH ? g_wf2l : g_wf1l;
    float* __restrict__ outp = WHICH ? g_buf2 : g_buf1;
    extern __shared__ __align__(16) char smc[];
    __nv_bfloat16* bufh = (__nv_bfloat16*)smc;
    __nv_bfloat16* bufl = (__nv_bfloat16*)(smc + HS);
    int tid = threadIdx.x;
    int zo = blockIdx.x >> 5, y0 = (blockIdx.x & 31) * 2;
    constexpr int CHUNKS = CI / 16;
    for (int it = tid; it < 528 * CHUNKS; it += 256) {
        int slot = it / CHUNKS, ch = it - slot * CHUNKS;
        int sz = slot / 264, r = slot - sz * 264;
        int sy = r / 66, sx = r - sy * 66;
        int zz = zo - 1 + sz, yy = y0 - 1 + sy, xx = sx - 1;
        bool ok = (zz >= 0) & (zz < ZIN) & (yy >= 0) & (yy < 64) & (xx >= 0) & (xx < 64);
        uint4 u[4];
        if (ok) {
            const uint4* src = (const uint4*)(in + ((size_t)zz * HW + yy * 64 + xx) * CI + ch * 16);
            u[0] = src[0]; u[1] = src[1]; u[2] = src[2]; u[3] = src[3];
        } else u[0] = u[1] = u[2] = u[3] = make_uint4(0, 0, 0, 0);
        uint32_t* uu = (uint32_t*)u;
        uint4 h0, h1, l0, l1;
        h0.x = __byte_perm(uu[0], uu[1], 0x5410);  h0.y = __byte_perm(uu[2], uu[3], 0x5410);
        h0.z = __byte_perm(uu[4], uu[5], 0x5410);  h0.w = __byte_perm(uu[6], uu[7], 0x5410);
        h1.x = __byte_perm(uu[8], uu[9], 0x5410);  h1.y = __byte_perm(uu[10], uu[11], 0x5410);
        h1.z = __byte_perm(uu[12], uu[13], 0x5410); h1.w = __byte_perm(uu[14], uu[15], 0x5410);
        l0.x = __byte_perm(uu[0], uu[1], 0x7632);  l0.y = __byte_perm(uu[2], uu[3], 0x7632);
        l0.z = __byte_perm(uu[4], uu[5], 0x7632);  l0.w = __byte_perm(uu[6], uu[7], 0x7632);
        l1.x = __byte_perm(uu[8], uu[9], 0x7632);  l1.y = __byte_perm(uu[10], uu[11], 0x7632);
        l1.z = __byte_perm(uu[12], uu[13], 0x7632); l1.w = __byte_perm(uu[14], uu[15], 0x7632);
        int base = slot * CIP + ch * 16;
        *(uint4*)(bufh + base) = h0; *(uint4*)(bufh + base + 8) = h1;
        *(uint4*)(bufl + base) = l0; *(uint4*)(bufl + base + 8) = l1;
    }
    __syncthreads();
    int w = tid >> 5, l = tid & 31;
    int cg = w >> 1, py = w & 1;
    float acc[8][4] = {};
    uint32_t sbh = smem_u32(bufh);
    for (int tap = 0; tap < 18; tap++) {
        int kz = tap / 9, rr = tap % 9, ky = rr / 3, kx = rr % 3;
        int slot0 = (kz * 4 + py + ky) * 66 + kx;
        uint32_t baddr0 = sbh + (uint32_t)((slot0 + (l & 7)) * CIP) * 2 + ((l >> 3) & 1) * 16;
        int widx = (tap * NK) * 128 + cg * 32 + l;
#pragma unroll
        for (int ks = 0; ks < NK; ks++) {
            uint4 ah = __ldg(wfh + widx + ks * 128);
            uint4 al = __ldg(wfl + widx + ks * 128);
            uint32_t ba = baddr0 + ks * 32;
#pragma unroll
            for (int t = 0; t < 8; t++) {
                uint32_t b0h, b1h, b0l, b1l;
                ldsm_x2(b0h, b1h, ba);
                ldsm_x2(b0l, b1l, ba + HS);
                mma_bf16(acc[t], ah, b0h, b1h);
                mma_bf16(acc[t], al, b0h, b1h);
                mma_bf16(acc[t], ah, b0l, b1l);
                ba += 8 * CIP * 2;
            }
        }
    }
    __syncthreads();
    float* cs = (float*)smc;
    {
        int co = cg * 16 + (l >> 2);
        int p0 = py * 64 + (l & 3) * 2;
#pragma unroll
        for (int t = 0; t < 8; t++) {
            int p = p0 + t * 8;
            cs[co * 128 + p] = acc[t][0];  cs[co * 128 + p + 1] = acc[t][1];
            cs[(co + 8) * 128 + p] = acc[t][2]; cs[(co + 8) * 128 + p + 1] = acc[t][3];
        }
    }
    __syncthreads();
    {
        float4* dstb = (float4*)(outp + (size_t)zo * HW + y0 * 64);
        size_t cstride = (size_t)ZOUT * HW / 4;
        for (int i = tid; i < 2048; i += 256) {
            int c = i >> 5, j = i & 31;
            dstb[c * cstride + j] = ((float4*)(cs + c * 128))[j];
        }
    }
    {
        int c = tid >> 2, q = tid & 3;
        float s = 0, q2 = 0;
#pragma unroll
        for (int j = 0; j < 32; j++) { float v = cs[c * 128 + q * 32 + j]; s += v; q2 += v * v; }
#pragma unroll
        for (int o = 2; o > 0; o >>= 1) {
            s += __shfl_down_sync(0xffffffffu, s, o);
            q2 += __shfl_down_sync(0xffffffffu, q2, o);
        }
        __shared__ float ps[64], pq[64];
        if (q == 0) { ps[c] = s; pq[c] = q2; }
        __syncthreads();
        if (tid < 64) {
            atomicAdd(&g_dsum[WHICH][tid], (double)ps[tid]);
            atomicAdd(&g_dsq[WHICH][tid], (double)pq[tid]);
        }
    }
}

__global__ __launch_bounds__(256) void k_h(const float* __restrict__ gg, const float* __restrict__ bb) {
    int base = (blockIdx.x * 256 + threadIdx.x) * 4;
    int c = base >> 17, off = base & 131071;
    float sc = g_istd[1][c] * gg[c], sh = bb[c] - g_mean[1][c] * sc;
    float4 r = *(const float4*)(g_buf2 + (size_t)c * (Z2 * HW) + off);
    float4 o;
    o.x = flrelu(fmaf(r.x, sc, sh)); o.y = flrelu(fmaf(r.y, sc, sh));
    o.z = flrelu(fmaf(r.z, sc, sh)); o.w = flrelu(fmaf(r.w, sc, sh));
    *(float4*)(g_h + base) = o;
}

__global__ __launch_bounds__(256) void k_dw(const float* __restrict__ w) {
    const int tileR = blockIdx.x * 16, z = blockIdx.y, c = blockIdx.z;
    __shared__ __align__(16) float ins[18 * 68];
    const int tx = threadIdx.x, ty = threadIdx.y, tid = ty * 16 + tx;
    float wv[9];
#pragma unroll
    for (int i = 0; i < 9; i++) wv[i] = __ldg(w + c * 9 + i);
    const float* xp = g_h + ((size_t)c * ZD + z) * HW;
    for (int i = tid; i < 18 * 68; i += 256) {
        int r = i / 68, c2 = i - r * 68, gr = tileR + r - 1, gc = c2 - 1;
        ins[i] = (gr >= 0 && gr < 64 && gc >= 0 && gc < 64) ? xp[gr * 64 + gc] : 0.f;
    }
    __syncthreads();
    float a0 = 0, a1 = 0, a2 = 0, a3 = 0;
#pragma unroll
    for (int ky = 0; ky < 3; ky++) {
        const float4* rp = (const float4*)(ins + (ty + ky) * 68 + (tx << 2));
        float4 va = rp[0], vb = rp[1];
        float w0 = wv[3 * ky], w1 = wv[3 * ky + 1], w2 = wv[3 * ky + 2];
        a0 = fmaf(w0, va.x, fmaf(w1, va.y, fmaf(w2, va.z, a0)));
        a1 = fmaf(w0, va.y, fmaf(w1, va.z, fmaf(w2, va.w, a1)));
        a2 = fmaf(w0, va.z, fmaf(w1, va.w, fmaf(w2, vb.x, a2)));
        a3 = fmaf(w0, va.w, fmaf(w1, vb.x, fmaf(w2, vb.y, a3)));
    }
    *(float4*)(g_dw + ((size_t)c * ZD + z) * HW + (tileR + ty) * 64 + (tx << 2)) = make_float4(a0, a1, a2, a3);
}

__global__ __launch_bounds__(256) void k_pw(const float* __restrict__ w) {
    __shared__ __align__(16) float wsm[64 * 64];
    int tid = threadIdx.x;
    for (int i = tid; i < 4096; i += 256) wsm[i] = w[(i & 63) * 64 + (i >> 6)];
    __syncthreads();
    int p = blockIdx.x * 256 + tid;
    float acc[64];
#pragma unroll
    for (int co = 0; co < 64; co++) acc[co] = 0.f;
    for (int ci = 0; ci < 64; ci++) {
        float v = g_dw[(size_t)ci * (ZD * HW) + p];
        const float4* wr = (const float4*)(wsm + ci * 64);
#pragma unroll
        for (int c4 = 0; c4 < 16; c4++) {
            float4 wv = wr[c4];
            acc[c4 * 4] = fmaf(wv.x, v, acc[c4 * 4]);
            acc[c4 * 4 + 1] = fmaf(wv.y, v, acc[c4 * 4 + 1]);
            acc[c4 * 4 + 2] = fmaf(wv.z, v, acc[c4 * 4 + 2]);
            acc[c4 * 4 + 3] = fmaf(wv.w, v, acc[c4 * 4 + 3]);
        }
    }
#pragma unroll
    for (int co = 0; co < 64; co++) g_pw[(size_t)co * (ZD * HW) + p] = acc[co];
}

__global__ __launch_bounds__(256) void k_statsR() {
    int c = blockIdx.x, tid = threadIdx.x;
    size_t base = (size_t)c * (ZD * HW) + (size_t)blockIdx.y * 32768;
    float s = 0, q = 0;
    for (int i = tid; i < 32768; i += 256) { float v = g_pw[base + i]; s += v; q += v * v; }
    stat_reduce_256(s, q, tid, &g_dsum[2][c], &g_dsq[2][c]);
}

__global__ __launch_bounds__(256) void k_x2t(const float* __restrict__ gg, const float* __restrict__ bb) {
    int z = blockIdx.y, n0 = blockIdx.x * 32, tid = threadIdx.x;
    __shared__ float sm[64][33];
    for (int i = tid; i < 2048; i += 256) {
        int c = i >> 5, nn = i & 31;
        size_t off = (size_t)c * (ZD * HW) + (size_t)z * HW + n0 + nn;
        float sc = g_istd[2][c] * gg[c], sh = bb[c] - g_mean[2][c] * sc;
        sm[c][nn] = g_h[off] + fsilu(fmaf(g_pw[off], sc, sh));
    }
    __syncthreads();
    for (int i = tid; i < 2048; i += 256) {
        int nn = i >> 6, c = i & 63;
        g_x2t[((size_t)(n0 + nn) * ZD + z) * 64 + c] = sm[c][nn];
    }
}

// LN + in_proj via mma.sync (tokens t0..t0+127)
__global__ __launch_bounds__(512) void k_inprojM(const float* __restrict__ lg, const float* __restrict__ lb) {
    extern __shared__ __align__(16) char smi[];
    __nv_bfloat16* th = (__nv_bfloat16*)smi;          // [128][72]
    __nv_bfloat16* tl = th + 128 * 72;
    int tid = threadIdx.x, w = tid >> 5, l = tid & 31;
    int t0 = blockIdx.x * 128;
    float g0 = lg[l], g1 = lg[l + 32], b0 = lb[l], b1 = lb[l + 32];
    for (int tt = w; tt < 128; tt += 16) {
        float v0 = g_x2t[(size_t)(t0 + tt) * 64 + l], v1 = g_x2t[(size_t)(t0 + tt) * 64 + l + 32];
        float s = v0 + v1, q = v0 * v0 + v1 * v1;
#pragma unroll
        for (int o = 16; o > 0; o >>= 1) {
            s += __shfl_xor_sync(0xffffffffu, s, o);
            q += __shfl_xor_sync(0xffffffffu, q, o);
        }
        float mean = s * (1.f / 64.f), var = q * (1.f / 64.f) - mean * mean;
        float istd = rsqrtf(var + EPSF);
        float n0 = (v0 - mean) * istd * g0 + b0, n1 = (v1 - mean) * istd * g1 + b1;
        __nv_bfloat16 h0 = __float2bfloat16(n0), h1 = __float2bfloat16(n1);
        th[tt * 72 + l] = h0;      tl[tt * 72 + l] = __float2bfloat16(n0 - __bfloat162float(h0));
        th[tt * 72 + l + 32] = h1; tl[tt * 72 + l + 32] = __float2bfloat16(n1 - __bfloat162float(h1));
    }
    __syncthreads();
    int cg = w;
    float acc[16][4] = {};
    uint32_t sbh = smem_u32(th);
    const uint32_t HS = 128 * 72 * 2;
#pragma unroll
    for (int ks = 0; ks < 4; ks++) {
        uint4 ah = __ldg(g_wih + (ks * 16 + cg) * 32 + l);
        uint4 al = __ldg(g_wil + (ks * 16 + cg) * 32 + l);
        uint32_t ba = sbh + (l & 7) * 144 + ((l >> 3) & 1) * 16 + ks * 32;
#pragma unroll
        for (int t = 0; t < 16; t++) {
            uint32_t b0h, b1h, b0l, b1l;
            ldsm_x2(b0h, b1h, ba);
            ldsm_x2(b0l, b1l, ba + HS);
            mma_bf16(acc[t], ah, b0h, b1h);
            mma_bf16(acc[t], al, b0h, b1h);
            mma_bf16(acc[t], ah, b0l, b1l);
            ba += 8 * 144;
        }
    }
    __syncthreads();
    float* cs = (float*)smi;   // [256][133]
    {
        int o = cg * 16 + (l >> 2), tc = (l & 3) * 2;
#pragma unroll
        for (int t = 0; t < 16; t++) {
            int tok = t * 8 + tc;
            cs[o * 133 + tok] = acc[t][0];       cs[o * 133 + tok + 1] = acc[t][1];
            cs[(o + 8) * 133 + tok] = acc[t][2]; cs[(o + 8) * 133 + tok + 1] = acc[t][3];
        }
    }
    __syncthreads();
    for (int i = tid; i < 32768; i += 512) {
        int t = i >> 8, j = i & 255;
        float v = cs[j * 133 + t];
        if (j < 128) g_xin[(size_t)(t0 + t) * 128 + j] = v;
        else         g_zg[(size_t)(t0 + t) * 128 + j - 128] = v;
    }
}

__global__ __launch_bounds__(128) void k_conv1d(const float* __restrict__ w, const float* __restrict__ b) {
    int n = blockIdx.x, d = threadIdx.x;
    __shared__ float sx[4096];
    size_t nb = (size_t)n * 4096;
    for (int i = d; i < 4096; i += 128) sx[i] = g_xin[nb + i];
    __syncthreads();
    float4 wv = ((const float4*)w)[d];
    float bias = b[d], x0 = 0, x1 = 0, x2v = 0;
#pragma unroll 4
    for (int z = 0; z < ZD; z++) {
        float xn = sx[z * 128 + d];
        float v = fmaf(wv.x, x0, fmaf(wv.y, x1, fmaf(wv.z, x2v, fmaf(wv.w, xn, bias))));
        g_xa[nb + z * 128 + d] = fsilu(v);
        x0 = x1; x1 = x2v; x2v = xn;
    }
}

__global__ __launch_bounds__(576) void k_xproj(const float* __restrict__ W) {
    __shared__ __align__(16) float xs[16][132];
    __shared__ __align__(16) float wx[36][132];
    int tid = threadIdx.x, t0 = blockIdx.x * 16;
    for (int i = tid; i < 2048; i += 576) xs[i >> 7][i & 127] = g_xa[(size_t)(t0 + (i >> 7)) * DI + (i & 127)];
    for (int i = tid; i < 4608; i += 576) wx[i >> 7][i & 127] = W[i];
    __syncthreads();
    int j = tid % 36, tl = tid / 36;
    float acc = 0;
#pragma unroll
    for (int d4 = 0; d4 < 32; d4++) {
        float4 xa = *(const float4*)&xs[tl][d4 * 4];
        float4 wv = *(const float4*)&wx[j][d4 * 4];
        acc = fmaf(xa.x, wv.x, fmaf(xa.y, wv.y, fmaf(xa.z, wv.z, fmaf(xa.w, wv.w, acc))));
    }
    g_xdbl[(size_t)(t0 + tl) * 36 + j] = acc;
}

__global__ __launch_bounds__(128) void k_scan(const float* __restrict__ dtw,
                                              const float* __restrict__ dtb, const float* __restrict__ Dp_) {
    int n = blockIdx.x, d = threadIdx.x;
    __shared__ __align__(16) float sxd[1152];
    __shared__ float su[4096], szg[4096];
    size_t nb = (size_t)n * 4096;
    for (int i = d; i < 1152; i += 128) sxd[i] = g_xdbl[(size_t)n * 1152 + i];
    for (int i = d; i < 4096; i += 128) { su[i] = g_xa[nb + i]; szg[i] = g_zg[nb + i]; }
    __syncthreads();
    float4 wdt = ((const float4*)dtw)[d];
    float bdt = dtb[d], Dp = Dp_[d];
    float A[DST];
    bool fast = true;
#pragma unroll
    for (int s = 0; s < DST; s++) {
        A[s] = g_A[d * DST + s];
        fast = fast && (fabsf(A[s] + (float)(s + 1)) <= 2e-6f * (float)(s + 1));
    }
    float st[DST];
#pragma unroll
    for (int s = 0; s < DST; s++) st[s] = 0.f;
    for (int z = 0; z < ZD; z++) {
        const float* xz = sxd + z * 36;
        float4 h0 = *(const float4*)xz;
        float Bv[16], Cv[16];
#pragma unroll
        for (int k = 0; k < 4; k++) {
            float4 bb4 = *(const float4*)(xz + 4 + 4 * k);
            float4 cc4 = *(const float4*)(xz + 20 + 4 * k);
            Bv[4 * k] = bb4.x; Bv[4 * k + 1] = bb4.y; Bv[4 * k + 2] = bb4.z; Bv[4 * k + 3] = bb4.w;
            Cv[4 * k] = cc4.x; Cv[4 * k + 1] = cc4.y; Cv[4 * k + 2] = cc4.z; Cv[4 * k + 3] = cc4.w;
        }
        float pre = fmaf(wdt.x, h0.x, fmaf(wdt.y, h0.y, fmaf(wdt.z, h0.z, fmaf(wdt.w, h0.w, bdt))));
        float dt = (pre > 15.f) ? pre : log1pf(__expf(pre));
        float u = su[z * 128 + d], du = dt * u, yv = 0;
        if (fast) {
            float E = __expf(-dt), ep = E;
#pragma unroll
            for (int s = 0; s < DST; s++) {
                st[s] = fmaf(ep, st[s], du * Bv[s]);
                yv = fmaf(st[s], Cv[s], yv);
                ep *= E;
            }
        } else {
#pragma unroll
            for (int s = 0; s < DST; s++) {
                float e = __expf(dt * A[s]);
                st[s] = fmaf(e, st[s], du * Bv[s]);
                yv = fmaf(st[s], Cv[s], yv);
            }
        }
        g_y[nb + z * 128 + d] = fmaf(Dp, u, yv) * fsilu(szg[z * 128 + d]);
    }
}

__global__ __launch_bounds__(256) void k_wc(const float* __restrict__ op, const float* __restrict__ pj) {
    int idx = blockIdx.x * 256 + threadIdx.x;
    if (idx >= 64 * 128) return;
    int o = idx >> 7, dd = idx & 127;
    float acc = 0;
#pragma unroll 8
    for (int c = 0; c < 64; c++) acc = fmaf(pj[o * 64 + c], op[c * 128 + dd], acc);
    g_wc[idx] = acc;
}

// out_proj via mma.sync + proj_b + fused pn stats
__global__ __launch_bounds__(256) void k_outprojM(const float* __restrict__ pb) {
    extern __shared__ __align__(16) char smo[];
    __nv_bfloat16* th = (__nv_bfloat16*)smo;          // [128][136]
    __nv_bfloat16* tl = th + 128 * 136;
    int tid = threadIdx.x, w = tid >> 5, l = tid & 31;
    int t0 = blockIdx.x * 128;
    for (int i = tid; i < 16384; i += 256) {
        int t = i >> 7, k = i & 127;
        float v = g_y[(size_t)(t0 + t) * 128 + k];
        __nv_bfloat16 hb = __float2bfloat16(v);
        th[t * 136 + k] = hb;
        tl[t * 136 + k] = __float2bfloat16(v - __bfloat162float(hb));
    }
    __syncthreads();
    int cg = w >> 1, py = w & 1;
    float acc[8][4] = {};
    uint32_t sbh = smem_u32(th);
    const uint32_t HS = 128 * 136 * 2;
#pragma unroll
    for (int ks = 0; ks < 8; ks++) {
        uint4 ah = __ldg(g_woh + (ks * 4 + cg) * 32 + l);
        uint4 al = __ldg(g_wol + (ks * 4 + cg) * 32 + l);
        uint32_t ba = sbh + py * 64 * 272 + (l & 7) * 272 + ((l >> 3) & 1) * 16 + ks * 32;
#pragma unroll
        for (int t = 0; t < 8; t++) {
            uint32_t b0h, b1h, b0l, b1l;
            ldsm_x2(b0h, b1h, ba);
            ldsm_x2(b0l, b1l, ba + HS);
            mma_bf16(acc[t], ah, b0h, b1h);
            mma_bf16(acc[t], al, b0h, b1h);
            mma_bf16(acc[t], ah, b0l, b1l);
            ba += 8 * 272;
        }
    }
    __syncthreads();
    float* cs = (float*)smo;   // [64][133]
    {
        int o = cg * 16 + (l >> 2), tc = py * 64 + (l & 3) * 2;
#pragma unroll
        for (int t = 0; t < 8; t++) {
            int tok = tc + t * 8;
            cs[o * 133 + tok] = acc[t][0];       cs[o * 133 + tok + 1] = acc[t][1];
            cs[(o + 8) * 133 + tok] = acc[t][2]; cs[(o + 8) * 133 + tok + 1] = acc[t][3];
        }
    }
    __syncthreads();
    for (int i = tid; i < 8192; i += 256) {
        int t = i >> 6, j = i & 63;
        g_seqout[(size_t)(t0 + t) * 64 + j] = cs[j * 133 + t] + pb[j];
    }
    {
        int c = tid >> 2, q = tid & 3;
        float bias = pb[c], s = 0, q2 = 0;
#pragma unroll
        for (int jj = 0; jj < 32; jj++) {
            float v = cs[c * 133 + q * 32 + jj] + bias;
            s += v; q2 += v * v;
        }
#pragma unroll
        for (int o = 2; o > 0; o >>= 1) {
            s += __shfl_down_sync(0xffffffffu, s, o);
            q2 += __shfl_down_sync(0xffffffffu, q2, o);
        }
        __shared__ float ps[64], pq[64];
        if (q == 0) { ps[c] = s; pq[c] = q2; }
        __syncthreads();
        if (tid < 64) {
            atomicAdd(&g_dsum[3][tid], (double)ps[tid]);
            atomicAdd(&g_dsq[3][tid], (double)pq[tid]);
        }
    }
}

__global__ __launch_bounds__(256) void k_final(const float* __restrict__ gg,
                                               const float* __restrict__ bb, float* __restrict__ out) {
    int z = blockIdx.y, n0 = blockIdx.x * 32, tid = threadIdx.x;
    __shared__ float sm[64][33];
    for (int i = tid; i < 2048; i += 256) {
        int nn = i >> 6, c = i & 63;
        sm[c][nn] = g_seqout[((size_t)(n0 + nn) * ZD + z) * 64 + c];
    }
    __syncthreads();
    for (int i = tid; i < 2048; i += 256) {
        int c = i >> 5, nn = i & 31;
        float sc = g_istd[3][c] * gg[c], sh = bb[c] - g_mean[3][c] * sc;
        size_t off = ((size_t)c * ZD + z) * HW + n0 + nn;
        out[off] = g_h[off] + fmaf(sm[c][nn], sc, sh);
    }
}

extern "C" void kernel_launch(void* const* d_in, const int* in_sizes, int n_in,
                              void* d_out, int out_size) {
    const float* x = (const float*)d_in[0];
    const float* c1_w = (const float*)d_in[1];
    const float* in1_g = (const float*)d_in[2];
    const float* in1_b = (const float*)d_in[3];
    const float* c2_w = (const float*)d_in[4];
    const float* in2_g = (const float*)d_in[5];
    const float* in2_b = (const float*)d_in[6];
    const float* dw_w = (const float*)d_in[7];
    const float* pw_w = (const float*)d_in[8];
    const float* inr_g = (const float*)d_in[9];
    const float* inr_b = (const float*)d_in[10];
    const float* ln_g = (const float*)d_in[11];
    const float* ln_b = (const float*)d_in[12];
    const float* in_proj_w = (const float*)d_in[13];
    const float* conv1d_w = (const float*)d_in[14];
    const float* conv1d_b = (const float*)d_in[15];
    const float* x_proj_w = (const float*)d_in[16];
    const float* dt_proj_w = (const float*)d_in[17];
    const float* dt_proj_b = (const float*)d_in[18];
    const float* A_log = (const float*)d_in[19];
    const float* D_p = (const float*)d_in[20];
    const float* out_proj_w = (const float*)d_in[21];
    const float* proj_w = (const float*)d_in[22];
    const float* proj_b = (const float*)d_in[23];
    const float* pn_g = (const float*)d_in[24];
    const float* pn_b = (const float*)d_in[25];
    float* out = (float*)d_out;

    const int SMEM1 = 2 * (2 * 4 * 66 * 40 * 2);
    const int SMEM2 = 2 * (2 * 4 * 66 * 72 * 2);
    const int SMEMI = 256 * 133 * 4;           // 136192
    const int SMEMO = 2 * 128 * 136 * 2;       // 69632
    cudaFuncSetAttribute(k_convM<0>, cudaFuncAttributeMaxDynamicSharedMemorySize, SMEM1);
    cudaFuncSetAttribute(k_convM<1>, cudaFuncAttributeMaxDynamicSharedMemorySize, SMEM2);
    cudaFuncSetAttribute(k_inprojM, cudaFuncAttributeMaxDynamicSharedMemorySize, SMEMI);
    cudaFuncSetAttribute(k_outprojM, cudaFuncAttributeMaxDynamicSharedMemorySize, SMEMO);

    dim3 b2d(16, 16);
    k_zero<<<1, 256>>>();
    k_prepA<<<8, 256>>>(A_log);
    k_prepx<<<ZD * 64, 256>>>(x);
    k_prepwf<0><<<18, 256>>>(c1_w);
    k_prepwf<1><<<36, 256>>>(c2_w);
    k_prepwi<<<8, 256>>>(in_proj_w);
    k_wc<<<32, 256>>>(out_proj_w, proj_w);
    k_prepwo<<<4, 256>>>();
    k_convM<0><<<Z1 * 32, 256, SMEM1>>>();
    k_fin<<<1, 64>>>(0);
    k_hn<<<Z1 * 64, 256>>>(in1_g, in1_b);
    k_convM<1><<<Z2 * 32, 256, SMEM2>>>();
    k_fin<<<1, 64>>>(1);
    k_h<<<8192, 256>>>(in2_g, in2_b);
    k_dw<<<dim3(4, ZD, CC), b2d>>>(dw_w);
    k_pw<<<512, 256>>>(pw_w);
    k_statsR<<<dim3(64, 4), 256>>>();
    k_fin<<<1, 64>>>(2);
    k_x2t<<<dim3(128, ZD), 256>>>(inr_g, inr_b);
    k_inprojM<<<NTOK / 128, 512, SMEMI>>>(ln_g, ln_b);
    k_conv1d<<<4096, 128>>>(conv1d_w, conv1d_b);
    k_xproj<<<NTOK / 16, 576>>>(x_proj_w);
    k_scan<<<4096, 128>>>(dt_proj_w, dt_proj_b, D_p);
    k_outprojM<<<NTOK / 128, 256, SMEMO>>>(proj_b);
    k_fin<<<1, 64>>>(3);
    k_final<<<dim3(128, ZD), 256>>>(pn_g, pn_b, out);
}